// round 1
// baseline (speedup 1.0000x reference)
#include <cuda_runtime.h>

#define SEQ   2048
#define BATCH 4
#define NH    16
#define DM    1024
#define HD    64

// Scratch: __device__ globals (no allocation allowed anywhere)
__device__ float g_q[BATCH * SEQ * DM];
__device__ float g_k[BATCH * SEQ * DM];
__device__ float g_v[BATCH * SEQ * DM];
__device__ float g_ctx[BATCH * SEQ * DM];

// ---------------------------------------------------------------------------
// SGEMM (NT): C[M,N] = A[M,K] * B[N,K]^T, all row-major, fp32.
// 128x128 block tile, BK=8, 256 threads, 8x8 micro-tile (split 4+4 rows/cols
// for conflict-free float4 smem reads).
// Requires M%128==0, N%128==0, K%8==0 (true for all call sites).
// ---------------------------------------------------------------------------
__global__ __launch_bounds__(256, 2)
void sgemm_nt(const float* __restrict__ A, const float* __restrict__ Bm,
              float* __restrict__ C, int M, int N, int K)
{
    __shared__ float As[8][128];
    __shared__ float Bs[8][128];

    const int tid  = threadIdx.x;
    const int tcol = tid & 15;          // 0..15 -> column groups
    const int trow = tid >> 4;          // 0..15 -> row groups
    const int row0 = blockIdx.y * 128;
    const int col0 = blockIdx.x * 128;

    // global->smem loaders: each thread loads one float4 of A and one of B
    const int lrow = tid >> 1;          // 0..127
    const int lk   = (tid & 1) << 2;    // 0 or 4
    const float* Ag = A  + (size_t)(row0 + lrow) * K + lk;
    const float* Bg = Bm + (size_t)(col0 + lrow) * K + lk;

    float c[8][8];
#pragma unroll
    for (int i = 0; i < 8; i++)
#pragma unroll
        for (int j = 0; j < 8; j++) c[i][j] = 0.0f;

    for (int kk = 0; kk < K; kk += 8) {
        float4 av = *(const float4*)(Ag + kk);
        float4 bv = *(const float4*)(Bg + kk);
        __syncthreads();   // previous compute phase done before overwriting smem
        As[lk + 0][lrow] = av.x;  As[lk + 1][lrow] = av.y;
        As[lk + 2][lrow] = av.z;  As[lk + 3][lrow] = av.w;
        Bs[lk + 0][lrow] = bv.x;  Bs[lk + 1][lrow] = bv.y;
        Bs[lk + 2][lrow] = bv.z;  Bs[lk + 3][lrow] = bv.w;
        __syncthreads();

#pragma unroll
        for (int k = 0; k < 8; k++) {
            float4 a0 = *(const float4*)&As[k][trow * 4];
            float4 a1 = *(const float4*)&As[k][64 + trow * 4];
            float4 b0 = *(const float4*)&Bs[k][tcol * 4];
            float4 b1 = *(const float4*)&Bs[k][64 + tcol * 4];
            float ar[8] = {a0.x, a0.y, a0.z, a0.w, a1.x, a1.y, a1.z, a1.w};
            float br[8] = {b0.x, b0.y, b0.z, b0.w, b1.x, b1.y, b1.z, b1.w};
#pragma unroll
            for (int i = 0; i < 8; i++)
#pragma unroll
                for (int j = 0; j < 8; j++)
                    c[i][j] += ar[i] * br[j];
        }
    }

    // epilogue: rows are {trow*4+i} and {64+trow*4+i}, cols likewise
#pragma unroll
    for (int i = 0; i < 8; i++) {
        int r = row0 + ((i < 4) ? (trow * 4 + i) : (64 + trow * 4 + (i - 4)));
        float4 v0 = make_float4(c[i][0], c[i][1], c[i][2], c[i][3]);
        float4 v1 = make_float4(c[i][4], c[i][5], c[i][6], c[i][7]);
        *(float4*)&C[(size_t)r * N + col0 + tcol * 4]      = v0;
        *(float4*)&C[(size_t)r * N + col0 + 64 + tcol * 4] = v1;
    }
}

// ---------------------------------------------------------------------------
// Causal flash attention, fp32. One block per (q-block of 64 rows, b*h).
// q/k/v/ctx layout: (b, s, h*64+e)  i.e. row-major (8192, 1024).
// 256 threads = 16x16 grid, 4x4 micro-tiles over the 64x64 score tile.
// smem rows padded to 68 floats (16B-aligned, low-conflict transposed stores).
// ---------------------------------------------------------------------------
#define PAD 68
#define FLASH_SMEM (4 * 64 * PAD * 4)

__global__ __launch_bounds__(256)
void flash_kernel(const float* __restrict__ qg, const float* __restrict__ kg,
                  const float* __restrict__ vg, float* __restrict__ ctx)
{
    extern __shared__ float sm[];
    float* Qs = sm;                 // [e][r]  (k-major)
    float* Ks = sm + 64 * PAD;      // [e][c]  (k-major)
    float* Vs = sm + 2 * 64 * PAD;  // [j][e]
    float* Ps = sm + 3 * 64 * PAD;  // [r][c]

    const int tid = threadIdx.x;
    const int tx  = tid & 15;       // column group (4 cols)
    const int ty  = tid >> 4;       // row group (4 rows)
    const int qb  = blockIdx.x;
    const int b   = blockIdx.y >> 4;
    const int h   = blockIdx.y & 15;
    const int q0  = qb * 64;

    const float* qbase = qg + (size_t)b * SEQ * DM + h * HD;
    const float* kbase = kg + (size_t)b * SEQ * DM + h * HD;
    const float* vbase = vg + (size_t)b * SEQ * DM + h * HD;

    // load Q tile, pre-scaled by 1/sqrt(64)
    for (int idx = tid; idx < 64 * 64; idx += 256) {
        int r = idx >> 6, e = idx & 63;
        Qs[e * PAD + r] = qbase[(size_t)(q0 + r) * DM + e] * 0.125f;
    }

    float m_i[4], l_i[4], acc[4][4];
#pragma unroll
    for (int i = 0; i < 4; i++) {
        m_i[i] = -1e30f; l_i[i] = 0.0f;
#pragma unroll
        for (int j = 0; j < 4; j++) acc[i][j] = 0.0f;
    }

    for (int kb = 0; kb <= qb; kb++) {
        const int k0 = kb * 64;
        __syncthreads();  // everyone done with previous Ks/Vs/Ps (also covers Q load)
        for (int idx = tid; idx < 64 * 64; idx += 256) {
            int cc = idx >> 6, e = idx & 63;
            float kvv = kbase[(size_t)(k0 + cc) * DM + e];
            float vvv = vbase[(size_t)(k0 + cc) * DM + e];
            Ks[e * PAD + cc] = kvv;
            Vs[cc * PAD + e] = vvv;
        }
        __syncthreads();

        // S = (Q/8) K^T   (64x64, 4x4 per thread)
        float s[4][4];
#pragma unroll
        for (int i = 0; i < 4; i++)
#pragma unroll
            for (int j = 0; j < 4; j++) s[i][j] = 0.0f;

#pragma unroll 16
        for (int e = 0; e < 64; e++) {
            float4 q4 = *(const float4*)&Qs[e * PAD + ty * 4];
            float4 k4 = *(const float4*)&Ks[e * PAD + tx * 4];
            float qr[4] = {q4.x, q4.y, q4.z, q4.w};
            float kr[4] = {k4.x, k4.y, k4.z, k4.w};
#pragma unroll
            for (int i = 0; i < 4; i++)
#pragma unroll
                for (int j = 0; j < 4; j++)
                    s[i][j] += qr[i] * kr[j];
        }

        // causal mask on diagonal block only (kb==qb): col > row -> -inf
        if (kb == qb) {
#pragma unroll
            for (int i = 0; i < 4; i++)
#pragma unroll
                for (int j = 0; j < 4; j++)
                    if (tx * 4 + j > ty * 4 + i) s[i][j] = -1e30f;
        }

        // online softmax (row stats reduced across the 16 tx lanes of the group)
#pragma unroll
        for (int i = 0; i < 4; i++) {
            float rm = fmaxf(fmaxf(s[i][0], s[i][1]), fmaxf(s[i][2], s[i][3]));
            rm = fmaxf(rm, __shfl_xor_sync(0xffffffffu, rm, 1));
            rm = fmaxf(rm, __shfl_xor_sync(0xffffffffu, rm, 2));
            rm = fmaxf(rm, __shfl_xor_sync(0xffffffffu, rm, 4));
            rm = fmaxf(rm, __shfl_xor_sync(0xffffffffu, rm, 8));
            float mnew  = fmaxf(m_i[i], rm);
            float alpha = __expf(m_i[i] - mnew);
            m_i[i] = mnew;
            float rs = 0.0f;
#pragma unroll
            for (int j = 0; j < 4; j++) {
                s[i][j] = __expf(s[i][j] - mnew);
                rs += s[i][j];
            }
            rs += __shfl_xor_sync(0xffffffffu, rs, 1);
            rs += __shfl_xor_sync(0xffffffffu, rs, 2);
            rs += __shfl_xor_sync(0xffffffffu, rs, 4);
            rs += __shfl_xor_sync(0xffffffffu, rs, 8);
            l_i[i] = l_i[i] * alpha + rs;
#pragma unroll
            for (int j = 0; j < 4; j++) acc[i][j] *= alpha;
        }

        // stash P
#pragma unroll
        for (int i = 0; i < 4; i++)
#pragma unroll
            for (int j = 0; j < 4; j++)
                Ps[(ty * 4 + i) * PAD + tx * 4 + j] = s[i][j];
        __syncthreads();

        // O += P V   (64x64x64)
#pragma unroll 8
        for (int j = 0; j < 64; j++) {
            float4 v4 = *(const float4*)&Vs[j * PAD + tx * 4];
            float vr[4] = {v4.x, v4.y, v4.z, v4.w};
#pragma unroll
            for (int i = 0; i < 4; i++) {
                float p = Ps[(ty * 4 + i) * PAD + j];
                acc[i][0] += p * vr[0];
                acc[i][1] += p * vr[1];
                acc[i][2] += p * vr[2];
                acc[i][3] += p * vr[3];
            }
        }
    }

    // epilogue: normalize and write ctx in (b, s, h*64+e) layout
#pragma unroll
    for (int i = 0; i < 4; i++) {
        float inv = 1.0f / l_i[i];
        float4 o = make_float4(acc[i][0] * inv, acc[i][1] * inv,
                               acc[i][2] * inv, acc[i][3] * inv);
        *(float4*)&ctx[(size_t)(b * SEQ + q0 + ty * 4 + i) * DM + h * HD + tx * 4] = o;
    }
}

// ---------------------------------------------------------------------------
extern "C" void kernel_launch(void* const* d_in, const int* in_sizes, int n_in,
                              void* d_out, int out_size)
{
    const float* x  = (const float*)d_in[0];
    const float* Wq = (const float*)d_in[1];
    const float* Wk = (const float*)d_in[2];
    const float* Wv = (const float*)d_in[3];
    const float* Wo = (const float*)d_in[4];
    float* out = (float*)d_out;

    float *q, *k, *v, *ctx;
    cudaGetSymbolAddress((void**)&q,   g_q);
    cudaGetSymbolAddress((void**)&k,   g_k);
    cudaGetSymbolAddress((void**)&v,   g_v);
    cudaGetSymbolAddress((void**)&ctx, g_ctx);

    cudaFuncSetAttribute(flash_kernel,
                         cudaFuncAttributeMaxDynamicSharedMemorySize, FLASH_SMEM);

    const int M = BATCH * SEQ;            // 8192
    dim3 gproj(DM / 128, M / 128);        // (8, 64)

    // QKV projections: C = X * W^T  (W is (H*E, D) contiguous = (1024, 1024))
    sgemm_nt<<<gproj, 256>>>(x, Wq, q, M, DM, DM);
    sgemm_nt<<<gproj, 256>>>(x, Wk, k, M, DM, DM);
    sgemm_nt<<<gproj, 256>>>(x, Wv, v, M, DM, DM);

    // causal attention
    flash_kernel<<<dim3(SEQ / 64, BATCH * NH), 256, FLASH_SMEM>>>(q, k, v, ctx);

    // output projection: out = ctx * Wo^T
    sgemm_nt<<<gproj, 256>>>(ctx, Wo, out, M, DM, DM);
}

// round 4
// speedup vs baseline: 1.4741x; 1.4741x over previous
#include <cuda_runtime.h>
#include <cuda_bf16.h>
#include <cstdint>

#define SEQ   2048
#define BATCH 4
#define NH    16
#define DM    1024
#define HD    64

// ---------------------------------------------------------------------------
// Scratch (__device__ globals; no allocation allowed anywhere)
// ---------------------------------------------------------------------------
__device__ float g_q[BATCH * SEQ * DM];
__device__ float g_k[BATCH * SEQ * DM];
__device__ float g_v[BATCH * SEQ * DM];
__device__ float g_ctx[BATCH * SEQ * DM];

__device__ __align__(256) __nv_bfloat16 g_xh[BATCH * SEQ * DM];
__device__ __align__(256) __nv_bfloat16 g_xl[BATCH * SEQ * DM];
__device__ __align__(256) __nv_bfloat16 g_ch[BATCH * SEQ * DM];
__device__ __align__(256) __nv_bfloat16 g_cl[BATCH * SEQ * DM];
__device__ __align__(256) __nv_bfloat16 g_wqh[DM * DM];
__device__ __align__(256) __nv_bfloat16 g_wql[DM * DM];
__device__ __align__(256) __nv_bfloat16 g_wkh[DM * DM];
__device__ __align__(256) __nv_bfloat16 g_wkl[DM * DM];
__device__ __align__(256) __nv_bfloat16 g_wvh[DM * DM];
__device__ __align__(256) __nv_bfloat16 g_wvl[DM * DM];
__device__ __align__(256) __nv_bfloat16 g_woh[DM * DM];
__device__ __align__(256) __nv_bfloat16 g_wol[DM * DM];

// ---------------------------------------------------------------------------
// Baseline-PTX helpers (mma.sync / ldmatrix / cp.async — legal on sm_100)
// ---------------------------------------------------------------------------
__device__ __forceinline__ uint32_t smem_u32(const void* p) {
    uint32_t a;
    asm("{ .reg .u64 t; cvta.to.shared.u64 t, %1; cvt.u32.u64 %0, t; }"
        : "=r"(a) : "l"(p));
    return a;
}

__device__ __forceinline__ void ldmx4(uint32_t* r, uint32_t addr) {
    asm volatile("ldmatrix.sync.aligned.m8n8.x4.shared.b16 {%0,%1,%2,%3}, [%4];"
                 : "=r"(r[0]), "=r"(r[1]), "=r"(r[2]), "=r"(r[3]) : "r"(addr));
}

__device__ __forceinline__ void mma_bf16(float* c, const uint32_t* a,
                                         uint32_t b0, uint32_t b1) {
    asm volatile(
        "mma.sync.aligned.m16n8k16.row.col.f32.bf16.bf16.f32 "
        "{%0,%1,%2,%3}, {%4,%5,%6,%7}, {%8,%9}, {%0,%1,%2,%3};"
        : "+f"(c[0]), "+f"(c[1]), "+f"(c[2]), "+f"(c[3])
        : "r"(a[0]), "r"(a[1]), "r"(a[2]), "r"(a[3]), "r"(b0), "r"(b1));
}

#define CP_ASYNC16(dst, src) \
    asm volatile("cp.async.cg.shared.global [%0], [%1], 16;" \
                 :: "r"(dst), "l"(src) : "memory")
#define CP_COMMIT()  asm volatile("cp.async.commit_group;" ::: "memory")
#define CP_WAIT(n)   asm volatile("cp.async.wait_group %0;" :: "n"(n) : "memory")

// ---------------------------------------------------------------------------
// fp32 -> (hi, lo) bf16 split, vectorized by 4
// ---------------------------------------------------------------------------
__global__ void split_f32(const float* __restrict__ in,
                          __nv_bfloat16* __restrict__ hi,
                          __nv_bfloat16* __restrict__ lo, int n4)
{
    int i = blockIdx.x * blockDim.x + threadIdx.x;
    if (i >= n4) return;
    float4 v = ((const float4*)in)[i];
    __nv_bfloat16 h0 = __float2bfloat16(v.x);
    __nv_bfloat16 h1 = __float2bfloat16(v.y);
    __nv_bfloat16 h2 = __float2bfloat16(v.z);
    __nv_bfloat16 h3 = __float2bfloat16(v.w);
    __nv_bfloat16 l0 = __float2bfloat16(v.x - __bfloat162float(h0));
    __nv_bfloat16 l1 = __float2bfloat16(v.y - __bfloat162float(h1));
    __nv_bfloat16 l2 = __float2bfloat16(v.z - __bfloat162float(h2));
    __nv_bfloat16 l3 = __float2bfloat16(v.w - __bfloat162float(h3));
    __nv_bfloat162* hp = (__nv_bfloat162*)hi;
    __nv_bfloat162* lp = (__nv_bfloat162*)lo;
    hp[2 * i]     = __nv_bfloat162{h0, h1};
    hp[2 * i + 1] = __nv_bfloat162{h2, h3};
    lp[2 * i]     = __nv_bfloat162{l0, l1};
    lp[2 * i + 1] = __nv_bfloat162{l2, l3};
}

// ---------------------------------------------------------------------------
// Split-bf16 mma.sync GEMM (NT): C[M,N] = (Ah+Al)[M,K] * ((Bh+Bl)[N,K])^T
//   C = Ah*Bh + Ah*Bl + Al*Bh   (lo*lo dropped, ~2^-18 relative)
// 128x128 CTA tile, BK=32, 8 warps (2x4), warp tile 64x32, m16n8k16.
// cp.async double-buffered smem, pad-40 rows for conflict-free ldmatrix.
// ---------------------------------------------------------------------------
#define LDS       40                    // padded row stride in bf16 (80 B)
#define TILE_E    (128 * LDS)           // elems per tile buffer
#define TILE_B2   (TILE_E * 2)          // bytes per tile buffer (10240)
#define STAGE_B2  (4 * TILE_B2)         // Ah, Al, Bh, Bl  (40960 B)
#define GEMM_SMEM (2 * STAGE_B2)        // double buffer    (81920 B)

__global__ __launch_bounds__(256, 1)
void gemm_mma(const __nv_bfloat16* __restrict__ Ah,
              const __nv_bfloat16* __restrict__ Al,
              const __nv_bfloat16* __restrict__ Bh,
              const __nv_bfloat16* __restrict__ Bl,
              float* __restrict__ C, int M, int N, int K)
{
    extern __shared__ char dsm[];
    const uint32_t smb = smem_u32(dsm);

    const int tid  = threadIdx.x;
    const int lane = tid & 31;
    const int wid  = tid >> 5;
    const int wm   = wid & 1;           // 0..1 (64-row strip)
    const int wn   = wid >> 1;          // 0..3 (32-col strip)
    const int row0 = blockIdx.y * 128;
    const int col0 = blockIdx.x * 128;

    const __nv_bfloat16* gsrc[4] = {
        Ah + (size_t)row0 * K, Al + (size_t)row0 * K,
        Bh + (size_t)col0 * K, Bl + (size_t)col0 * K
    };

    // cp.async per-thread chunks: 2 x 16B per tile per stage
    const int ch0 = tid, ch1 = tid + 256;
    const int r0c = ch0 >> 2, c0c = ch0 & 3;
    const int r1c = ch1 >> 2, c1c = ch1 & 3;
    const uint32_t d0 = (uint32_t)(r0c * LDS + c0c * 8) * 2;
    const uint32_t d1 = (uint32_t)(r1c * LDS + c1c * 8) * 2;

    // ldmatrix per-lane base offsets (elements)
    const int aq = lane >> 3, ar = lane & 7;
    const uint32_t aoff = (uint32_t)(((aq & 1) * 8 + ar) * LDS + (aq >> 1) * 8);
    const int sub = lane >> 3, br = lane & 7;
    const uint32_t boff = (uint32_t)(((sub >> 1) * 8 + br) * LDS + (sub & 1) * 8);

    float acc[4][4][4];
#pragma unroll
    for (int i = 0; i < 4; i++)
#pragma unroll
        for (int j = 0; j < 4; j++)
#pragma unroll
            for (int r = 0; r < 4; r++) acc[i][j][r] = 0.0f;

    const int KSTAGES = K / 32;

    // preload stage 0
    {
        const uint32_t sb = smb;
#pragma unroll
        for (int t = 0; t < 4; t++) {
            const __nv_bfloat16* g = gsrc[t];
            CP_ASYNC16(sb + t * TILE_B2 + d0, g + (size_t)r0c * K + c0c * 8);
            CP_ASYNC16(sb + t * TILE_B2 + d1, g + (size_t)r1c * K + c1c * 8);
        }
        CP_COMMIT();
    }

#pragma unroll 1
    for (int kt = 0; kt < KSTAGES; kt++) {
        if (kt + 1 < KSTAGES) {
            const uint32_t sb = smb + ((kt + 1) & 1) * STAGE_B2;
            const int kk = (kt + 1) * 32;
#pragma unroll
            for (int t = 0; t < 4; t++) {
                const __nv_bfloat16* g = gsrc[t];
                CP_ASYNC16(sb + t * TILE_B2 + d0, g + (size_t)r0c * K + kk + c0c * 8);
                CP_ASYNC16(sb + t * TILE_B2 + d1, g + (size_t)r1c * K + kk + c1c * 8);
            }
            CP_COMMIT();
            CP_WAIT(1);
        } else {
            CP_WAIT(0);
        }
        __syncthreads();

        const uint32_t sb  = smb + (kt & 1) * STAGE_B2;
        const uint32_t sAh = sb;
        const uint32_t sAl = sb + TILE_B2;
        const uint32_t sBh = sb + 2 * TILE_B2;
        const uint32_t sBl = sb + 3 * TILE_B2;

#pragma unroll
        for (int ks = 0; ks < 2; ks++) {
            uint32_t ah[4][4], al[4][4], bh[2][4], bl[2][4];
#pragma unroll
            for (int i = 0; i < 4; i++) {
                uint32_t o = (aoff + (uint32_t)((wm * 64 + i * 16) * LDS + ks * 16)) * 2;
                ldmx4(ah[i], sAh + o);
                ldmx4(al[i], sAl + o);
            }
#pragma unroll
            for (int p = 0; p < 2; p++) {
                uint32_t o = (boff + (uint32_t)((wn * 32 + p * 16) * LDS + ks * 16)) * 2;
                ldmx4(bh[p], sBh + o);
                ldmx4(bl[p], sBl + o);
            }
#pragma unroll
            for (int i = 0; i < 4; i++) {
#pragma unroll
                for (int j = 0; j < 4; j++) {
                    const int p = j >> 1, jj = j & 1;
                    mma_bf16(acc[i][j], ah[i], bh[p][2 * jj], bh[p][2 * jj + 1]);
                    mma_bf16(acc[i][j], ah[i], bl[p][2 * jj], bl[p][2 * jj + 1]);
                    mma_bf16(acc[i][j], al[i], bh[p][2 * jj], bh[p][2 * jj + 1]);
                }
            }
        }
        __syncthreads();
    }

    // epilogue: direct float2 stores (fragment c0,c1 = row l/4; c2,c3 = +8)
    const int mbase = row0 + wm * 64 + (lane >> 2);
    const int nbase = col0 + wn * 32 + (lane & 3) * 2;
#pragma unroll
    for (int i = 0; i < 4; i++) {
#pragma unroll
        for (int j = 0; j < 4; j++) {
            const int r = mbase + i * 16;
            const int c = nbase + j * 8;
            *(float2*)&C[(size_t)r * N + c]       = make_float2(acc[i][j][0], acc[i][j][1]);
            *(float2*)&C[(size_t)(r + 8) * N + c] = make_float2(acc[i][j][2], acc[i][j][3]);
        }
    }
}

// ---------------------------------------------------------------------------
// Causal flash attention, fp32 (unchanged — round-4 target)
// ---------------------------------------------------------------------------
#define PAD 68
#define FLASH_SMEM (4 * 64 * PAD * 4)

__global__ __launch_bounds__(256)
void flash_kernel(const float* __restrict__ qg, const float* __restrict__ kg,
                  const float* __restrict__ vg, float* __restrict__ ctx)
{
    extern __shared__ float smf[];
    float* Qs = smf;
    float* Ks = smf + 64 * PAD;
    float* Vs = smf + 2 * 64 * PAD;
    float* Ps = smf + 3 * 64 * PAD;

    const int tid = threadIdx.x;
    const int tx  = tid & 15;
    const int ty  = tid >> 4;
    const int qb  = blockIdx.x;
    const int b   = blockIdx.y >> 4;
    const int h   = blockIdx.y & 15;
    const int q0  = qb * 64;

    const float* qbase = qg + (size_t)b * SEQ * DM + h * HD;
    const float* kbase = kg + (size_t)b * SEQ * DM + h * HD;
    const float* vbase = vg + (size_t)b * SEQ * DM + h * HD;

    for (int idx = tid; idx < 64 * 64; idx += 256) {
        int r = idx >> 6, e = idx & 63;
        Qs[e * PAD + r] = qbase[(size_t)(q0 + r) * DM + e] * 0.125f;
    }

    float m_i[4], l_i[4], acc[4][4];
#pragma unroll
    for (int i = 0; i < 4; i++) {
        m_i[i] = -1e30f; l_i[i] = 0.0f;
#pragma unroll
        for (int j = 0; j < 4; j++) acc[i][j] = 0.0f;
    }

    for (int kb = 0; kb <= qb; kb++) {
        const int k0 = kb * 64;
        __syncthreads();
        for (int idx = tid; idx < 64 * 64; idx += 256) {
            int cc = idx >> 6, e = idx & 63;
            Ks[e * PAD + cc] = kbase[(size_t)(k0 + cc) * DM + e];
            Vs[cc * PAD + e] = vbase[(size_t)(k0 + cc) * DM + e];
        }
        __syncthreads();

        float s[4][4];
#pragma unroll
        for (int i = 0; i < 4; i++)
#pragma unroll
            for (int j = 0; j < 4; j++) s[i][j] = 0.0f;

#pragma unroll 16
        for (int e = 0; e < 64; e++) {
            float4 q4 = *(const float4*)&Qs[e * PAD + ty * 4];
            float4 k4 = *(const float4*)&Ks[e * PAD + tx * 4];
            float qr[4] = {q4.x, q4.y, q4.z, q4.w};
            float kr[4] = {k4.x, k4.y, k4.z, k4.w};
#pragma unroll
            for (int i = 0; i < 4; i++)
#pragma unroll
                for (int j = 0; j < 4; j++)
                    s[i][j] += qr[i] * kr[j];
        }

        if (kb == qb) {
#pragma unroll
            for (int i = 0; i < 4; i++)
#pragma unroll
                for (int j = 0; j < 4; j++)
                    if (tx * 4 + j > ty * 4 + i) s[i][j] = -1e30f;
        }

#pragma unroll
        for (int i = 0; i < 4; i++) {
            float rm = fmaxf(fmaxf(s[i][0], s[i][1]), fmaxf(s[i][2], s[i][3]));
            rm = fmaxf(rm, __shfl_xor_sync(0xffffffffu, rm, 1));
            rm = fmaxf(rm, __shfl_xor_sync(0xffffffffu, rm, 2));
            rm = fmaxf(rm, __shfl_xor_sync(0xffffffffu, rm, 4));
            rm = fmaxf(rm, __shfl_xor_sync(0xffffffffu, rm, 8));
            float mnew  = fmaxf(m_i[i], rm);
            float alpha = __expf(m_i[i] - mnew);
            m_i[i] = mnew;
            float rs = 0.0f;
#pragma unroll
            for (int j = 0; j < 4; j++) {
                s[i][j] = __expf(s[i][j] - mnew);
                rs += s[i][j];
            }
            rs += __shfl_xor_sync(0xffffffffu, rs, 1);
            rs += __shfl_xor_sync(0xffffffffu, rs, 2);
            rs += __shfl_xor_sync(0xffffffffu, rs, 4);
            rs += __shfl_xor_sync(0xffffffffu, rs, 8);
            l_i[i] = l_i[i] * alpha + rs;
#pragma unroll
            for (int j = 0; j < 4; j++) acc[i][j] *= alpha;
        }

#pragma unroll
        for (int i = 0; i < 4; i++)
#pragma unroll
            for (int j = 0; j < 4; j++)
                Ps[(ty * 4 + i) * PAD + tx * 4 + j] = s[i][j];
        __syncthreads();

#pragma unroll 8
        for (int j = 0; j < 64; j++) {
            float4 v4 = *(const float4*)&Vs[j * PAD + tx * 4];
            float vr[4] = {v4.x, v4.y, v4.z, v4.w};
#pragma unroll
            for (int i = 0; i < 4; i++) {
                float p = Ps[(ty * 4 + i) * PAD + j];
                acc[i][0] += p * vr[0];
                acc[i][1] += p * vr[1];
                acc[i][2] += p * vr[2];
                acc[i][3] += p * vr[3];
            }
        }
    }

#pragma unroll
    for (int i = 0; i < 4; i++) {
        float inv = 1.0f / l_i[i];
        float4 o = make_float4(acc[i][0] * inv, acc[i][1] * inv,
                               acc[i][2] * inv, acc[i][3] * inv);
        *(float4*)&ctx[(size_t)(b * SEQ + q0 + ty * 4 + i) * DM + h * HD + tx * 4] = o;
    }
}

// ---------------------------------------------------------------------------
extern "C" void kernel_launch(void* const* d_in, const int* in_sizes, int n_in,
                              void* d_out, int out_size)
{
    const float* x  = (const float*)d_in[0];
    const float* Wq = (const float*)d_in[1];
    const float* Wk = (const float*)d_in[2];
    const float* Wv = (const float*)d_in[3];
    const float* Wo = (const float*)d_in[4];
    float* out = (float*)d_out;

    float *q, *k, *v, *ctx;
    cudaGetSymbolAddress((void**)&q,   g_q);
    cudaGetSymbolAddress((void**)&k,   g_k);
    cudaGetSymbolAddress((void**)&v,   g_v);
    cudaGetSymbolAddress((void**)&ctx, g_ctx);

    __nv_bfloat16 *xh, *xl, *ch, *cl;
    __nv_bfloat16 *wqh, *wql, *wkh, *wkl, *wvh, *wvl, *woh, *wol;
    cudaGetSymbolAddress((void**)&xh, g_xh);
    cudaGetSymbolAddress((void**)&xl, g_xl);
    cudaGetSymbolAddress((void**)&ch, g_ch);
    cudaGetSymbolAddress((void**)&cl, g_cl);
    cudaGetSymbolAddress((void**)&wqh, g_wqh);
    cudaGetSymbolAddress((void**)&wql, g_wql);
    cudaGetSymbolAddress((void**)&wkh, g_wkh);
    cudaGetSymbolAddress((void**)&wkl, g_wkl);
    cudaGetSymbolAddress((void**)&wvh, g_wvh);
    cudaGetSymbolAddress((void**)&wvl, g_wvl);
    cudaGetSymbolAddress((void**)&woh, g_woh);
    cudaGetSymbolAddress((void**)&wol, g_wol);

    cudaFuncSetAttribute(flash_kernel,
                         cudaFuncAttributeMaxDynamicSharedMemorySize, FLASH_SMEM);
    cudaFuncSetAttribute(gemm_mma,
                         cudaFuncAttributeMaxDynamicSharedMemorySize, GEMM_SMEM);

    const int M  = BATCH * SEQ;           // 8192
    const int n4x = M * DM / 4;
    const int n4w = DM * DM / 4;

    // fp32 -> bf16 hi/lo splits
    split_f32<<<n4x / 256, 256>>>(x, xh, xl, n4x);
    split_f32<<<n4w / 256, 256>>>(Wq, wqh, wql, n4w);
    split_f32<<<n4w / 256, 256>>>(Wk, wkh, wkl, n4w);
    split_f32<<<n4w / 256, 256>>>(Wv, wvh, wvl, n4w);
    split_f32<<<n4w / 256, 256>>>(Wo, woh, wol, n4w);

    // QKV projections on tensor cores (mma.sync)
    dim3 gproj(DM / 128, M / 128);        // (8, 64) = 512 CTAs
    gemm_mma<<<gproj, 256, GEMM_SMEM>>>(xh, xl, wqh, wql, q, M, DM, DM);
    gemm_mma<<<gproj, 256, GEMM_SMEM>>>(xh, xl, wkh, wkl, k, M, DM, DM);
    gemm_mma<<<gproj, 256, GEMM_SMEM>>>(xh, xl, wvh, wvl, v, M, DM, DM);

    // causal attention (fp32)
    flash_kernel<<<dim3(SEQ / 64, BATCH * NH), 256, FLASH_SMEM>>>(q, k, v, ctx);

    // output projection
    split_f32<<<n4x / 256, 256>>>(ctx, ch, cl, n4x);
    gemm_mma<<<gproj, 256, GEMM_SMEM>>>(ch, cl, woh, wol, out, M, DM, DM);
}

// round 6
// speedup vs baseline: 2.3707x; 1.6082x over previous
#include <cuda_runtime.h>
#include <cuda_bf16.h>
#include <cstdint>

#define SEQ   2048
#define BATCH 4
#define NH    16
#define DM    1024
#define HD    64

// ---------------------------------------------------------------------------
// Scratch (__device__ globals; no allocation allowed anywhere)
// ---------------------------------------------------------------------------
__device__ __align__(256) __nv_bfloat16 g_xh[BATCH * SEQ * DM];
__device__ __align__(256) __nv_bfloat16 g_xl[BATCH * SEQ * DM];
__device__ __align__(256) __nv_bfloat16 g_qh[BATCH * SEQ * DM];
__device__ __align__(256) __nv_bfloat16 g_ql[BATCH * SEQ * DM];
__device__ __align__(256) __nv_bfloat16 g_kh[BATCH * SEQ * DM];
__device__ __align__(256) __nv_bfloat16 g_kl[BATCH * SEQ * DM];
__device__ __align__(256) __nv_bfloat16 g_vh[BATCH * SEQ * DM];
__device__ __align__(256) __nv_bfloat16 g_vl[BATCH * SEQ * DM];
__device__ __align__(256) __nv_bfloat16 g_ch[BATCH * SEQ * DM];
__device__ __align__(256) __nv_bfloat16 g_cl[BATCH * SEQ * DM];
__device__ __align__(256) __nv_bfloat16 g_wqh[DM * DM];
__device__ __align__(256) __nv_bfloat16 g_wql[DM * DM];
__device__ __align__(256) __nv_bfloat16 g_wkh[DM * DM];
__device__ __align__(256) __nv_bfloat16 g_wkl[DM * DM];
__device__ __align__(256) __nv_bfloat16 g_wvh[DM * DM];
__device__ __align__(256) __nv_bfloat16 g_wvl[DM * DM];
__device__ __align__(256) __nv_bfloat16 g_woh[DM * DM];
__device__ __align__(256) __nv_bfloat16 g_wol[DM * DM];

// ---------------------------------------------------------------------------
// Baseline-PTX helpers (mma.sync / ldmatrix / cp.async — legal on sm_100)
// ---------------------------------------------------------------------------
__device__ __forceinline__ uint32_t smem_u32(const void* p) {
    uint32_t a;
    asm("{ .reg .u64 t; cvta.to.shared.u64 t, %1; cvt.u32.u64 %0, t; }"
        : "=r"(a) : "l"(p));
    return a;
}

__device__ __forceinline__ void ldmx4(uint32_t* r, uint32_t addr) {
    asm volatile("ldmatrix.sync.aligned.m8n8.x4.shared.b16 {%0,%1,%2,%3}, [%4];"
                 : "=r"(r[0]), "=r"(r[1]), "=r"(r[2]), "=r"(r[3]) : "r"(addr));
}

__device__ __forceinline__ void ldmx4t(uint32_t* r, uint32_t addr) {
    asm volatile("ldmatrix.sync.aligned.m8n8.x4.trans.shared.b16 {%0,%1,%2,%3}, [%4];"
                 : "=r"(r[0]), "=r"(r[1]), "=r"(r[2]), "=r"(r[3]) : "r"(addr));
}

__device__ __forceinline__ void mma_bf16(float* c, const uint32_t* a,
                                         uint32_t b0, uint32_t b1) {
    asm volatile(
        "mma.sync.aligned.m16n8k16.row.col.f32.bf16.bf16.f32 "
        "{%0,%1,%2,%3}, {%4,%5,%6,%7}, {%8,%9}, {%0,%1,%2,%3};"
        : "+f"(c[0]), "+f"(c[1]), "+f"(c[2]), "+f"(c[3])
        : "r"(a[0]), "r"(a[1]), "r"(a[2]), "r"(a[3]), "r"(b0), "r"(b1));
}

#define CP_ASYNC16(dst, src) \
    asm volatile("cp.async.cg.shared.global [%0], [%1], 16;" \
                 :: "r"(dst), "l"(src) : "memory")
#define CP_COMMIT()  asm volatile("cp.async.commit_group;" ::: "memory")
#define CP_WAIT(n)   asm volatile("cp.async.wait_group %0;" :: "n"(n) : "memory")

// pack two fp32 into bf16x2 reg: low half = lo, high half = hi (intrinsic, arch-safe)
__device__ __forceinline__ uint32_t packh(float lo, float hi) {
    __nv_bfloat162 t = __floats2bfloat162_rn(lo, hi);
    return *(uint32_t*)&t;
}

// exp(0.125 * d) for d <= 0, via 2^t with deg-6 poly on r in [-0.5, 0.5].
// All FMA-pipe ops — no MUFU. |rel err| < 2e-7.
__device__ __forceinline__ float fexp_raw(float d) {
    float t = fmaxf(d * 0.18033688011112042f, -115.0f);  // 0.125*log2(e)
    int   e = __float2int_rn(t);
    float r = t - (float)e;
    float p = 1.5403530393e-4f;
    p = fmaf(p, r, 1.3333558146e-3f);
    p = fmaf(p, r, 9.6181291076e-3f);
    p = fmaf(p, r, 5.5504108665e-2f);
    p = fmaf(p, r, 2.4022650696e-1f);
    p = fmaf(p, r, 6.9314718056e-1f);
    p = fmaf(p, r, 1.0f);
    return __int_as_float(__float_as_int(p) + (e << 23));
}

// ---------------------------------------------------------------------------
// fp32 -> (hi, lo) bf16 split, vectorized by 4
// ---------------------------------------------------------------------------
__global__ void split_f32(const float* __restrict__ in,
                          __nv_bfloat16* __restrict__ hi,
                          __nv_bfloat16* __restrict__ lo, int n4)
{
    int i = blockIdx.x * blockDim.x + threadIdx.x;
    if (i >= n4) return;
    float4 v = ((const float4*)in)[i];
    __nv_bfloat16 h0 = __float2bfloat16(v.x);
    __nv_bfloat16 h1 = __float2bfloat16(v.y);
    __nv_bfloat16 h2 = __float2bfloat16(v.z);
    __nv_bfloat16 h3 = __float2bfloat16(v.w);
    __nv_bfloat16 l0 = __float2bfloat16(v.x - __bfloat162float(h0));
    __nv_bfloat16 l1 = __float2bfloat16(v.y - __bfloat162float(h1));
    __nv_bfloat16 l2 = __float2bfloat16(v.z - __bfloat162float(h2));
    __nv_bfloat16 l3 = __float2bfloat16(v.w - __bfloat162float(h3));
    __nv_bfloat162* hp = (__nv_bfloat162*)hi;
    __nv_bfloat162* lp = (__nv_bfloat162*)lo;
    hp[2 * i]     = __nv_bfloat162{h0, h1};
    hp[2 * i + 1] = __nv_bfloat162{h2, h3};
    lp[2 * i]     = __nv_bfloat162{l0, l1};
    lp[2 * i + 1] = __nv_bfloat162{l2, l3};
}

// ---------------------------------------------------------------------------
// Split-bf16 mma.sync GEMM (NT): C = (Ah+Al)(Bh+Bl)^T ≈ AhBh + AhBl + AlBh
// 128x128 CTA tile, BK=32, 8 warps (2x4), warp tile 64x32, m16n8k16.
// SPLIT=1: epilogue writes bf16 hi/lo pair (for q/k/v); SPLIT=0: fp32.
// ---------------------------------------------------------------------------
#define LDS       40
#define TILE_E    (128 * LDS)
#define TILE_B2   (TILE_E * 2)
#define STAGE_B2  (4 * TILE_B2)
#define GEMM_SMEM (2 * STAGE_B2)

template<int SPLIT>
__global__ __launch_bounds__(256, 1)
void gemm_mma(const __nv_bfloat16* __restrict__ Ah,
              const __nv_bfloat16* __restrict__ Al,
              const __nv_bfloat16* __restrict__ Bh,
              const __nv_bfloat16* __restrict__ Bl,
              float* __restrict__ C,
              __nv_bfloat16* __restrict__ Ch,
              __nv_bfloat16* __restrict__ Cl,
              int M, int N, int K)
{
    extern __shared__ char dsm[];
    const uint32_t smb = smem_u32(dsm);

    const int tid  = threadIdx.x;
    const int lane = tid & 31;
    const int wid  = tid >> 5;
    const int wm   = wid & 1;
    const int wn   = wid >> 1;
    const int row0 = blockIdx.y * 128;
    const int col0 = blockIdx.x * 128;

    const __nv_bfloat16* gsrc[4] = {
        Ah + (size_t)row0 * K, Al + (size_t)row0 * K,
        Bh + (size_t)col0 * K, Bl + (size_t)col0 * K
    };

    const int ch0 = tid, ch1 = tid + 256;
    const int r0c = ch0 >> 2, c0c = ch0 & 3;
    const int r1c = ch1 >> 2, c1c = ch1 & 3;
    const uint32_t d0 = (uint32_t)(r0c * LDS + c0c * 8) * 2;
    const uint32_t d1 = (uint32_t)(r1c * LDS + c1c * 8) * 2;

    const int aq = lane >> 3, ar = lane & 7;
    const uint32_t aoff = (uint32_t)(((aq & 1) * 8 + ar) * LDS + (aq >> 1) * 8);
    const uint32_t boff = (uint32_t)(((aq >> 1) * 8 + ar) * LDS + (aq & 1) * 8);

    float acc[4][4][4];
#pragma unroll
    for (int i = 0; i < 4; i++)
#pragma unroll
        for (int j = 0; j < 4; j++)
#pragma unroll
            for (int r = 0; r < 4; r++) acc[i][j][r] = 0.0f;

    const int KSTAGES = K / 32;

    {
        const uint32_t sb = smb;
#pragma unroll
        for (int t = 0; t < 4; t++) {
            const __nv_bfloat16* g = gsrc[t];
            CP_ASYNC16(sb + t * TILE_B2 + d0, g + (size_t)r0c * K + c0c * 8);
            CP_ASYNC16(sb + t * TILE_B2 + d1, g + (size_t)r1c * K + c1c * 8);
        }
        CP_COMMIT();
    }

#pragma unroll 1
    for (int kt = 0; kt < KSTAGES; kt++) {
        if (kt + 1 < KSTAGES) {
            const uint32_t sb = smb + ((kt + 1) & 1) * STAGE_B2;
            const int kk = (kt + 1) * 32;
#pragma unroll
            for (int t = 0; t < 4; t++) {
                const __nv_bfloat16* g = gsrc[t];
                CP_ASYNC16(sb + t * TILE_B2 + d0, g + (size_t)r0c * K + kk + c0c * 8);
                CP_ASYNC16(sb + t * TILE_B2 + d1, g + (size_t)r1c * K + kk + c1c * 8);
            }
            CP_COMMIT();
            CP_WAIT(1);
        } else {
            CP_WAIT(0);
        }
        __syncthreads();

        const uint32_t sb  = smb + (kt & 1) * STAGE_B2;
        const uint32_t sAh = sb;
        const uint32_t sAl = sb + TILE_B2;
        const uint32_t sBh = sb + 2 * TILE_B2;
        const uint32_t sBl = sb + 3 * TILE_B2;

#pragma unroll
        for (int ks = 0; ks < 2; ks++) {
            uint32_t ah[4][4], al[4][4], bh[2][4], bl[2][4];
#pragma unroll
            for (int i = 0; i < 4; i++) {
                uint32_t o = (aoff + (uint32_t)((wm * 64 + i * 16) * LDS + ks * 16)) * 2;
                ldmx4(ah[i], sAh + o);
                ldmx4(al[i], sAl + o);
            }
#pragma unroll
            for (int p = 0; p < 2; p++) {
                uint32_t o = (boff + (uint32_t)((wn * 32 + p * 16) * LDS + ks * 16)) * 2;
                ldmx4(bh[p], sBh + o);
                ldmx4(bl[p], sBl + o);
            }
#pragma unroll
            for (int i = 0; i < 4; i++) {
#pragma unroll
                for (int j = 0; j < 4; j++) {
                    const int p = j >> 1, jj = j & 1;
                    mma_bf16(acc[i][j], ah[i], bh[p][2 * jj], bh[p][2 * jj + 1]);
                    mma_bf16(acc[i][j], ah[i], bl[p][2 * jj], bl[p][2 * jj + 1]);
                    mma_bf16(acc[i][j], al[i], bh[p][2 * jj], bh[p][2 * jj + 1]);
                }
            }
        }
        __syncthreads();
    }

    const int mbase = row0 + wm * 64 + (lane >> 2);
    const int nbase = col0 + wn * 32 + (lane & 3) * 2;
#pragma unroll
    for (int i = 0; i < 4; i++) {
#pragma unroll
        for (int j = 0; j < 4; j++) {
            const int r = mbase + i * 16;
            const int c = nbase + j * 8;
            if (SPLIT) {
#pragma unroll
                for (int hrow = 0; hrow < 2; hrow++) {
                    float v0 = acc[i][j][2 * hrow];
                    float v1 = acc[i][j][2 * hrow + 1];
                    __nv_bfloat16 h0 = __float2bfloat16(v0);
                    __nv_bfloat16 h1 = __float2bfloat16(v1);
                    __nv_bfloat162 hv{h0, h1};
                    __nv_bfloat162 lv{__float2bfloat16(v0 - __bfloat162float(h0)),
                                      __float2bfloat16(v1 - __bfloat162float(h1))};
                    size_t off = (size_t)(r + 8 * hrow) * N + c;
                    *(__nv_bfloat162*)&Ch[off] = hv;
                    *(__nv_bfloat162*)&Cl[off] = lv;
                }
            } else {
                *(float2*)&C[(size_t)r * N + c]       = make_float2(acc[i][j][0], acc[i][j][1]);
                *(float2*)&C[(size_t)(r + 8) * N + c] = make_float2(acc[i][j][2], acc[i][j][3]);
            }
        }
    }
}

// ---------------------------------------------------------------------------
// Causal flash attention on mma.sync, split-bf16, FMA-pipe exp.
// Br=128 q-rows per CTA (8 warps x 16 rows), Bc=64 kv per tile.
// ---------------------------------------------------------------------------
#define FLDS      72                  // padded row stride (bf16), 144 B
#define QBUF_B    (128 * FLDS * 2)    // 18432
#define KVBUF_B   (64 * FLDS * 2)     // 9216
#define KVSTAGE_B (4 * KVBUF_B)       // 36864
#define FLASH_SMEM (2 * QBUF_B + 2 * KVSTAGE_B)   // 110592

__global__ __launch_bounds__(256, 1)
void flash_mma(const __nv_bfloat16* __restrict__ qh_g, const __nv_bfloat16* __restrict__ ql_g,
               const __nv_bfloat16* __restrict__ kh_g, const __nv_bfloat16* __restrict__ kl_g,
               const __nv_bfloat16* __restrict__ vh_g, const __nv_bfloat16* __restrict__ vl_g,
               __nv_bfloat16* __restrict__ ch_g, __nv_bfloat16* __restrict__ cl_g)
{
    extern __shared__ char dsm[];
    const uint32_t smb = smem_u32(dsm);
    const uint32_t sq  = smb;
    const uint32_t skv = smb + 2 * QBUF_B;

    const int tid  = threadIdx.x;
    const int lane = tid & 31;
    const int wid  = tid >> 5;
    const int qb   = blockIdx.x;           // 0..15
    const int b    = blockIdx.y >> 4;
    const int h    = blockIdx.y & 15;
    const int q0   = qb * 128;
    const size_t gbase = (size_t)b * SEQ * DM + h * HD;

    const int ar = lane & 7, asub = lane >> 3;
    const uint32_t aoff = (uint32_t)(((asub & 1) * 8 + ar) * FLDS + (asub >> 1) * 8);
    const uint32_t boff = (uint32_t)(((asub >> 1) * 8 + ar) * FLDS + (asub & 1) * 8);

    const __nv_bfloat16* kvsrc[4] = {kh_g, kl_g, vh_g, vl_g};

    // ---- kv tile 0 prefetch + Q load ----
    {
#pragma unroll
        for (int kk = 0; kk < 8; kk++) {
            int id = tid + kk * 256;
            int buf = id >> 9, row = (id >> 3) & 63, cc = id & 7;
            CP_ASYNC16(skv + buf * KVBUF_B + row * 144 + cc * 16,
                       kvsrc[buf] + gbase + (size_t)row * DM + cc * 8);
        }
        CP_COMMIT();
#pragma unroll
        for (int kk = 0; kk < 8; kk++) {
            int id = tid + kk * 256;
            int buf = id >> 10, row = (id >> 3) & 127, cc = id & 7;
            const __nv_bfloat16* src = (buf ? ql_g : qh_g) + gbase +
                                       (size_t)(q0 + row) * DM + cc * 8;
            CP_ASYNC16(sq + buf * QBUF_B + row * 144 + cc * 16, src);
        }
        CP_COMMIT();
        CP_WAIT(0);
        __syncthreads();
    }

    uint32_t qhf[4][4], qlf[4][4];
#pragma unroll
    for (int kc = 0; kc < 4; kc++) {
        uint32_t o = (aoff + (uint32_t)(wid * 16 * FLDS + kc * 16)) * 2;
        ldmx4(qhf[kc], sq + o);
        ldmx4(qlf[kc], sq + QBUF_B + o);
    }

    float acc[8][4];
#pragma unroll
    for (int f = 0; f < 8; f++)
#pragma unroll
        for (int r = 0; r < 4; r++) acc[f][r] = 0.0f;
    float m0 = -1e30f, m1 = -1e30f, l0 = 0.0f, l1 = 0.0f;

    const int T  = 2 * qb + 2;
    const int rr = lane >> 2, qx = lane & 3;
    const int rowg0 = q0 + wid * 16 + rr;

#pragma unroll 1
    for (int t = 0; t < T; t++) {
        if (t + 1 < T) {
            const uint32_t sb = skv + ((t + 1) & 1) * KVSTAGE_B;
            const int s1 = (t + 1) * 64;
#pragma unroll
            for (int kk = 0; kk < 8; kk++) {
                int id = tid + kk * 256;
                int buf = id >> 9, row = (id >> 3) & 63, cc = id & 7;
                CP_ASYNC16(sb + buf * KVBUF_B + row * 144 + cc * 16,
                           kvsrc[buf] + gbase + (size_t)(s1 + row) * DM + cc * 8);
            }
            CP_COMMIT();
            CP_WAIT(1);
        } else {
            CP_WAIT(0);
        }
        __syncthreads();

        const uint32_t st = skv + (t & 1) * KVSTAGE_B;

        // ---- S = Q K^T (split, 3 passes) ----
        float s[8][4];
#pragma unroll
        for (int f = 0; f < 8; f++)
#pragma unroll
            for (int r = 0; r < 4; r++) s[f][r] = 0.0f;

#pragma unroll
        for (int kc = 0; kc < 4; kc++) {
#pragma unroll
            for (int p = 0; p < 4; p++) {
                uint32_t o = (boff + (uint32_t)(p * 16 * FLDS + kc * 16)) * 2;
                uint32_t kbh[4], kbl[4];
                ldmx4(kbh, st + o);
                ldmx4(kbl, st + KVBUF_B + o);
                mma_bf16(s[2 * p],     qhf[kc], kbh[0], kbh[1]);
                mma_bf16(s[2 * p + 1], qhf[kc], kbh[2], kbh[3]);
                mma_bf16(s[2 * p],     qhf[kc], kbl[0], kbl[1]);
                mma_bf16(s[2 * p + 1], qhf[kc], kbl[2], kbl[3]);
                mma_bf16(s[2 * p],     qlf[kc], kbh[0], kbh[1]);
                mma_bf16(s[2 * p + 1], qlf[kc], kbh[2], kbh[3]);
            }
        }

        // ---- causal mask (diagonal tiles only) ----
        const int s0 = t * 64;
        if (s0 + 63 > q0) {
#pragma unroll
            for (int f = 0; f < 8; f++) {
                int c0 = s0 + f * 8 + 2 * qx;
                if (c0 > rowg0)         s[f][0] = -1e30f;
                if (c0 + 1 > rowg0)     s[f][1] = -1e30f;
                if (c0 > rowg0 + 8)     s[f][2] = -1e30f;
                if (c0 + 1 > rowg0 + 8) s[f][3] = -1e30f;
            }
        }

        // ---- online softmax (per half-row; quad shfl reductions) ----
        {
            float mx = -1e30f;
#pragma unroll
            for (int f = 0; f < 8; f++) mx = fmaxf(mx, fmaxf(s[f][0], s[f][1]));
            mx = fmaxf(mx, __shfl_xor_sync(0xffffffffu, mx, 1));
            mx = fmaxf(mx, __shfl_xor_sync(0xffffffffu, mx, 2));
            float mn = fmaxf(m0, mx);
            float al = fexp_raw(m0 - mn);
            m0 = mn;
            float sum = 0.0f;
#pragma unroll
            for (int f = 0; f < 8; f++) {
                s[f][0] = fexp_raw(s[f][0] - mn);
                s[f][1] = fexp_raw(s[f][1] - mn);
                sum += s[f][0] + s[f][1];
            }
            sum += __shfl_xor_sync(0xffffffffu, sum, 1);
            sum += __shfl_xor_sync(0xffffffffu, sum, 2);
            l0 = l0 * al + sum;
#pragma unroll
            for (int f = 0; f < 8; f++) { acc[f][0] *= al; acc[f][1] *= al; }
        }
        {
            float mx = -1e30f;
#pragma unroll
            for (int f = 0; f < 8; f++) mx = fmaxf(mx, fmaxf(s[f][2], s[f][3]));
            mx = fmaxf(mx, __shfl_xor_sync(0xffffffffu, mx, 1));
            mx = fmaxf(mx, __shfl_xor_sync(0xffffffffu, mx, 2));
            float mn = fmaxf(m1, mx);
            float al = fexp_raw(m1 - mn);
            m1 = mn;
            float sum = 0.0f;
#pragma unroll
            for (int f = 0; f < 8; f++) {
                s[f][2] = fexp_raw(s[f][2] - mn);
                s[f][3] = fexp_raw(s[f][3] - mn);
                sum += s[f][2] + s[f][3];
            }
            sum += __shfl_xor_sync(0xffffffffu, sum, 1);
            sum += __shfl_xor_sync(0xffffffffu, sum, 2);
            l1 = l1 * al + sum;
#pragma unroll
            for (int f = 0; f < 8; f++) { acc[f][2] *= al; acc[f][3] *= al; }
        }

        // ---- O += P V (split, 3 passes; P stays in registers) ----
#pragma unroll
        for (int jc = 0; jc < 4; jc++) {
            const float* sA = s[2 * jc];
            const float* sB = s[2 * jc + 1];
            uint32_t pha[4], pla[4];
            pha[0] = packh(sA[0], sA[1]);
            pha[1] = packh(sA[2], sA[3]);
            pha[2] = packh(sB[0], sB[1]);
            pha[3] = packh(sB[2], sB[3]);
            {
                float rA0 = sA[0] - __bfloat162float(__float2bfloat16(sA[0]));
                float rA1 = sA[1] - __bfloat162float(__float2bfloat16(sA[1]));
                float rA2 = sA[2] - __bfloat162float(__float2bfloat16(sA[2]));
                float rA3 = sA[3] - __bfloat162float(__float2bfloat16(sA[3]));
                float rB0 = sB[0] - __bfloat162float(__float2bfloat16(sB[0]));
                float rB1 = sB[1] - __bfloat162float(__float2bfloat16(sB[1]));
                float rB2 = sB[2] - __bfloat162float(__float2bfloat16(sB[2]));
                float rB3 = sB[3] - __bfloat162float(__float2bfloat16(sB[3]));
                pla[0] = packh(rA0, rA1);
                pla[1] = packh(rA2, rA3);
                pla[2] = packh(rB0, rB1);
                pla[3] = packh(rB2, rB3);
            }
#pragma unroll
            for (int pe = 0; pe < 4; pe++) {
                uint32_t o = (aoff + (uint32_t)(jc * 16 * FLDS + pe * 16)) * 2;
                uint32_t vbh[4], vbl[4];
                ldmx4t(vbh, st + 2 * KVBUF_B + o);
                ldmx4t(vbl, st + 3 * KVBUF_B + o);
                mma_bf16(acc[2 * pe],     pha, vbh[0], vbh[1]);
                mma_bf16(acc[2 * pe + 1], pha, vbh[2], vbh[3]);
                mma_bf16(acc[2 * pe],     pha, vbl[0], vbl[1]);
                mma_bf16(acc[2 * pe + 1], pha, vbl[2], vbl[3]);
                mma_bf16(acc[2 * pe],     pla, vbh[0], vbh[1]);
                mma_bf16(acc[2 * pe + 1], pla, vbh[2], vbh[3]);
            }
        }
        __syncthreads();
    }

    // ---- epilogue: normalize, split to bf16 hi/lo, store ----
    const float inv0 = 1.0f / l0;
    const float inv1 = 1.0f / l1;
#pragma unroll
    for (int f = 0; f < 8; f++) {
        const int coloff = f * 8 + 2 * qx;
#pragma unroll
        for (int hrow = 0; hrow < 2; hrow++) {
            float inv = hrow ? inv1 : inv0;
            float v0 = acc[f][2 * hrow]     * inv;
            float v1 = acc[f][2 * hrow + 1] * inv;
            __nv_bfloat16 h0 = __float2bfloat16(v0);
            __nv_bfloat16 h1 = __float2bfloat16(v1);
            __nv_bfloat162 hv{h0, h1};
            __nv_bfloat162 lv{__float2bfloat16(v0 - __bfloat162float(h0)),
                              __float2bfloat16(v1 - __bfloat162float(h1))};
            size_t off = gbase + (size_t)(rowg0 + 8 * hrow) * DM + coloff;
            *(__nv_bfloat162*)&ch_g[off] = hv;
            *(__nv_bfloat162*)&cl_g[off] = lv;
        }
    }
}

// ---------------------------------------------------------------------------
extern "C" void kernel_launch(void* const* d_in, const int* in_sizes, int n_in,
                              void* d_out, int out_size)
{
    const float* x  = (const float*)d_in[0];
    const float* Wq = (const float*)d_in[1];
    const float* Wk = (const float*)d_in[2];
    const float* Wv = (const float*)d_in[3];
    const float* Wo = (const float*)d_in[4];
    float* out = (float*)d_out;

    __nv_bfloat16 *xh, *xl, *qh, *ql, *kh, *kl, *vh, *vl, *ch, *cl;
    __nv_bfloat16 *wqh, *wql, *wkh, *wkl, *wvh, *wvl, *woh, *wol;
    cudaGetSymbolAddress((void**)&xh, g_xh);
    cudaGetSymbolAddress((void**)&xl, g_xl);
    cudaGetSymbolAddress((void**)&qh, g_qh);
    cudaGetSymbolAddress((void**)&ql, g_ql);
    cudaGetSymbolAddress((void**)&kh, g_kh);
    cudaGetSymbolAddress((void**)&kl, g_kl);
    cudaGetSymbolAddress((void**)&vh, g_vh);
    cudaGetSymbolAddress((void**)&vl, g_vl);
    cudaGetSymbolAddress((void**)&ch, g_ch);
    cudaGetSymbolAddress((void**)&cl, g_cl);
    cudaGetSymbolAddress((void**)&wqh, g_wqh);
    cudaGetSymbolAddress((void**)&wql, g_wql);
    cudaGetSymbolAddress((void**)&wkh, g_wkh);
    cudaGetSymbolAddress((void**)&wkl, g_wkl);
    cudaGetSymbolAddress((void**)&wvh, g_wvh);
    cudaGetSymbolAddress((void**)&wvl, g_wvl);
    cudaGetSymbolAddress((void**)&woh, g_woh);
    cudaGetSymbolAddress((void**)&wol, g_wol);

    cudaFuncSetAttribute(gemm_mma<0>,
                         cudaFuncAttributeMaxDynamicSharedMemorySize, GEMM_SMEM);
    cudaFuncSetAttribute(gemm_mma<1>,
                         cudaFuncAttributeMaxDynamicSharedMemorySize, GEMM_SMEM);
    cudaFuncSetAttribute(flash_mma,
                         cudaFuncAttributeMaxDynamicSharedMemorySize, FLASH_SMEM);

    const int M  = BATCH * SEQ;           // 8192
    const int n4x = M * DM / 4;
    const int n4w = DM * DM / 4;

    // fp32 -> bf16 hi/lo splits (input + weights only)
    split_f32<<<n4x / 256, 256>>>(x, xh, xl, n4x);
    split_f32<<<n4w / 256, 256>>>(Wq, wqh, wql, n4w);
    split_f32<<<n4w / 256, 256>>>(Wk, wkh, wkl, n4w);
    split_f32<<<n4w / 256, 256>>>(Wv, wvh, wvl, n4w);
    split_f32<<<n4w / 256, 256>>>(Wo, woh, wol, n4w);

    // QKV projections -> split bf16 outputs directly
    dim3 gproj(DM / 128, M / 128);
    gemm_mma<1><<<gproj, 256, GEMM_SMEM>>>(xh, xl, wqh, wql, nullptr, qh, ql, M, DM, DM);
    gemm_mma<1><<<gproj, 256, GEMM_SMEM>>>(xh, xl, wkh, wkl, nullptr, kh, kl, M, DM, DM);
    gemm_mma<1><<<gproj, 256, GEMM_SMEM>>>(xh, xl, wvh, wvl, nullptr, vh, vl, M, DM, DM);

    // causal attention on tensor cores -> split ctx
    flash_mma<<<dim3(SEQ / 128, BATCH * NH), 256, FLASH_SMEM>>>(
        qh, ql, kh, kl, vh, vl, ch, cl);

    // output projection (fp32 out)
    gemm_mma<0><<<gproj, 256, GEMM_SMEM>>>(ch, cl, woh, wol, out, nullptr, nullptr, M, DM, DM);
}

// round 9
// speedup vs baseline: 2.4102x; 1.0167x over previous
#include <cuda_runtime.h>
#include <cuda_bf16.h>
#include <cstdint>

#define SEQ   2048
#define BATCH 4
#define NH    16
#define DM    1024
#define HD    64

// ---------------------------------------------------------------------------
// Scratch (__device__ globals; no allocation allowed anywhere)
// ---------------------------------------------------------------------------
__device__ __align__(256) __nv_bfloat16 g_xh[BATCH * SEQ * DM];
__device__ __align__(256) __nv_bfloat16 g_xl[BATCH * SEQ * DM];
__device__ __align__(256) __nv_bfloat16 g_qh[BATCH * SEQ * DM];
__device__ __align__(256) __nv_bfloat16 g_ql[BATCH * SEQ * DM];
__device__ __align__(256) __nv_bfloat16 g_kh[BATCH * SEQ * DM];
__device__ __align__(256) __nv_bfloat16 g_kl[BATCH * SEQ * DM];
__device__ __align__(256) __nv_bfloat16 g_vh[BATCH * SEQ * DM];
__device__ __align__(256) __nv_bfloat16 g_vl[BATCH * SEQ * DM];
__device__ __align__(256) __nv_bfloat16 g_ch[BATCH * SEQ * DM];
__device__ __align__(256) __nv_bfloat16 g_cl[BATCH * SEQ * DM];
__device__ __align__(256) __nv_bfloat16 g_wqh[DM * DM];
__device__ __align__(256) __nv_bfloat16 g_wql[DM * DM];
__device__ __align__(256) __nv_bfloat16 g_wkh[DM * DM];
__device__ __align__(256) __nv_bfloat16 g_wkl[DM * DM];
__device__ __align__(256) __nv_bfloat16 g_wvh[DM * DM];
__device__ __align__(256) __nv_bfloat16 g_wvl[DM * DM];
__device__ __align__(256) __nv_bfloat16 g_woh[DM * DM];
__device__ __align__(256) __nv_bfloat16 g_wol[DM * DM];

// Q pre-scale: 0.125 * log2(e) — S arrives in log2 domain
#define QSCALE 0.18033688011112042f

// ---------------------------------------------------------------------------
// Baseline-PTX helpers (mma.sync / ldmatrix / cp.async — legal on sm_100)
// ---------------------------------------------------------------------------
__device__ __forceinline__ uint32_t smem_u32(const void* p) {
    uint32_t a;
    asm("{ .reg .u64 t; cvta.to.shared.u64 t, %1; cvt.u32.u64 %0, t; }"
        : "=r"(a) : "l"(p));
    return a;
}

__device__ __forceinline__ void ldmx4(uint32_t* r, uint32_t addr) {
    asm volatile("ldmatrix.sync.aligned.m8n8.x4.shared.b16 {%0,%1,%2,%3}, [%4];"
                 : "=r"(r[0]), "=r"(r[1]), "=r"(r[2]), "=r"(r[3]) : "r"(addr));
}

__device__ __forceinline__ void ldmx4t(uint32_t* r, uint32_t addr) {
    asm volatile("ldmatrix.sync.aligned.m8n8.x4.trans.shared.b16 {%0,%1,%2,%3}, [%4];"
                 : "=r"(r[0]), "=r"(r[1]), "=r"(r[2]), "=r"(r[3]) : "r"(addr));
}

__device__ __forceinline__ void mma_bf16(float* c, const uint32_t* a,
                                         uint32_t b0, uint32_t b1) {
    asm volatile(
        "mma.sync.aligned.m16n8k16.row.col.f32.bf16.bf16.f32 "
        "{%0,%1,%2,%3}, {%4,%5,%6,%7}, {%8,%9}, {%0,%1,%2,%3};"
        : "+f"(c[0]), "+f"(c[1]), "+f"(c[2]), "+f"(c[3])
        : "r"(a[0]), "r"(a[1]), "r"(a[2]), "r"(a[3]), "r"(b0), "r"(b1));
}

#define CP_ASYNC16(dst, src) \
    asm volatile("cp.async.cg.shared.global [%0], [%1], 16;" \
                 :: "r"(dst), "l"(src) : "memory")
#define CP_COMMIT()  asm volatile("cp.async.commit_group;" ::: "memory")
#define CP_WAIT(n)   asm volatile("cp.async.wait_group %0;" :: "n"(n) : "memory")

// pack two fp32 into bf16x2 reg (rn; intrinsic, arch-safe)
__device__ __forceinline__ uint32_t packh(float lo, float hi) {
    __nv_bfloat162 t = __floats2bfloat162_rn(lo, hi);
    return *(uint32_t*)&t;
}

// PRMT trunc-split helpers: hi pair = high halves of two fp32 (1 ALU op);
// residual = v - trunc16(v), exact in fp32.
__device__ __forceinline__ uint32_t pack_hi_trunc(float a, float b) {
    return __byte_perm(__float_as_uint(a), __float_as_uint(b), 0x7632);
}
__device__ __forceinline__ float resid16(float v) {
    return v - __uint_as_float(__float_as_uint(v) & 0xffff0000u);
}

// exp2(d) for d <= 0, deg-5 poly on r in [-0.5, 0.5]. FMA-pipe only.
__device__ __forceinline__ float fexp2_raw(float d) {
    float t = fmaxf(d, -115.0f);
    int   e = __float2int_rn(t);
    float r = t - (float)e;
    float p = 1.3333558146e-3f;
    p = fmaf(p, r, 9.6181291076e-3f);
    p = fmaf(p, r, 5.5504108665e-2f);
    p = fmaf(p, r, 2.4022650696e-1f);
    p = fmaf(p, r, 6.9314718056e-1f);
    p = fmaf(p, r, 1.0f);
    return __int_as_float(__float_as_int(p) + (e << 23));
}

// ---------------------------------------------------------------------------
// fp32 -> (hi, lo) bf16 trunc-split, vectorized by 4
// ---------------------------------------------------------------------------
__global__ void split_f32(const float* __restrict__ in,
                          __nv_bfloat16* __restrict__ hi,
                          __nv_bfloat16* __restrict__ lo, int n4)
{
    int i = blockIdx.x * blockDim.x + threadIdx.x;
    if (i >= n4) return;
    float4 v = ((const float4*)in)[i];
    uint32_t* hp = (uint32_t*)hi;
    uint32_t* lp = (uint32_t*)lo;
    hp[2 * i]     = pack_hi_trunc(v.x, v.y);
    hp[2 * i + 1] = pack_hi_trunc(v.z, v.w);
    lp[2 * i]     = packh(resid16(v.x), resid16(v.y));
    lp[2 * i + 1] = packh(resid16(v.z), resid16(v.w));
}

// ---------------------------------------------------------------------------
// Split-bf16 mma.sync GEMM (NT): C = (Ah+Al)(Bh+Bl)^T ≈ AhBh + AhBl + AlBh
// 128x128 CTA tile, BK=32, 8 warps (2x4), warp tile 64x32, m16n8k16.
// SPLIT=1: epilogue writes oscale*C as bf16 hi/lo pair; SPLIT=0: fp32.
// Launch bounds (256,1) — identical to the round-6 kernel that passed.
// ---------------------------------------------------------------------------
#define LDS       40
#define TILE_E    (128 * LDS)
#define TILE_B2   (TILE_E * 2)
#define STAGE_B2  (4 * TILE_B2)
#define GEMM_SMEM (2 * STAGE_B2)

template<int SPLIT>
__global__ __launch_bounds__(256, 1)
void gemm_mma(const __nv_bfloat16* __restrict__ Ah,
              const __nv_bfloat16* __restrict__ Al,
              const __nv_bfloat16* __restrict__ Bh,
              const __nv_bfloat16* __restrict__ Bl,
              float* __restrict__ C,
              __nv_bfloat16* __restrict__ Ch,
              __nv_bfloat16* __restrict__ Cl,
              float oscale,
              int M, int N, int K)
{
    extern __shared__ char dsm[];
    const uint32_t smb = smem_u32(dsm);

    const int tid  = threadIdx.x;
    const int lane = tid & 31;
    const int wid  = tid >> 5;
    const int wm   = wid & 1;
    const int wn   = wid >> 1;
    const int row0 = blockIdx.y * 128;
    const int col0 = blockIdx.x * 128;

    const __nv_bfloat16* gsrc[4] = {
        Ah + (size_t)row0 * K, Al + (size_t)row0 * K,
        Bh + (size_t)col0 * K, Bl + (size_t)col0 * K
    };

    const int ch0 = tid, ch1 = tid + 256;
    const int r0c = ch0 >> 2, c0c = ch0 & 3;
    const int r1c = ch1 >> 2, c1c = ch1 & 3;
    const uint32_t d0 = (uint32_t)(r0c * LDS + c0c * 8) * 2;
    const uint32_t d1 = (uint32_t)(r1c * LDS + c1c * 8) * 2;

    const int aq = lane >> 3, ar = lane & 7;
    const uint32_t aoff = (uint32_t)(((aq & 1) * 8 + ar) * LDS + (aq >> 1) * 8);
    const uint32_t boff = (uint32_t)(((aq >> 1) * 8 + ar) * LDS + (aq & 1) * 8);

    float acc[4][4][4];
#pragma unroll
    for (int i = 0; i < 4; i++)
#pragma unroll
        for (int j = 0; j < 4; j++)
#pragma unroll
            for (int r = 0; r < 4; r++) acc[i][j][r] = 0.0f;

    const int KSTAGES = K / 32;

    {
        const uint32_t sb = smb;
#pragma unroll
        for (int t = 0; t < 4; t++) {
            const __nv_bfloat16* g = gsrc[t];
            CP_ASYNC16(sb + t * TILE_B2 + d0, g + (size_t)r0c * K + c0c * 8);
            CP_ASYNC16(sb + t * TILE_B2 + d1, g + (size_t)r1c * K + c1c * 8);
        }
        CP_COMMIT();
    }

#pragma unroll 1
    for (int kt = 0; kt < KSTAGES; kt++) {
        if (kt + 1 < KSTAGES) {
            const uint32_t sb = smb + ((kt + 1) & 1) * STAGE_B2;
            const int kk = (kt + 1) * 32;
#pragma unroll
            for (int t = 0; t < 4; t++) {
                const __nv_bfloat16* g = gsrc[t];
                CP_ASYNC16(sb + t * TILE_B2 + d0, g + (size_t)r0c * K + kk + c0c * 8);
                CP_ASYNC16(sb + t * TILE_B2 + d1, g + (size_t)r1c * K + kk + c1c * 8);
            }
            CP_COMMIT();
            CP_WAIT(1);
        } else {
            CP_WAIT(0);
        }
        __syncthreads();

        const uint32_t sb  = smb + (kt & 1) * STAGE_B2;
        const uint32_t sAh = sb;
        const uint32_t sAl = sb + TILE_B2;
        const uint32_t sBh = sb + 2 * TILE_B2;
        const uint32_t sBl = sb + 3 * TILE_B2;

#pragma unroll
        for (int ks = 0; ks < 2; ks++) {
            uint32_t ah[4][4], al[4][4], bh[2][4], bl[2][4];
#pragma unroll
            for (int i = 0; i < 4; i++) {
                uint32_t o = (aoff + (uint32_t)((wm * 64 + i * 16) * LDS + ks * 16)) * 2;
                ldmx4(ah[i], sAh + o);
                ldmx4(al[i], sAl + o);
            }
#pragma unroll
            for (int p = 0; p < 2; p++) {
                uint32_t o = (boff + (uint32_t)((wn * 32 + p * 16) * LDS + ks * 16)) * 2;
                ldmx4(bh[p], sBh + o);
                ldmx4(bl[p], sBl + o);
            }
#pragma unroll
            for (int i = 0; i < 4; i++) {
#pragma unroll
                for (int j = 0; j < 4; j++) {
                    const int p = j >> 1, jj = j & 1;
                    mma_bf16(acc[i][j], ah[i], bh[p][2 * jj], bh[p][2 * jj + 1]);
                    mma_bf16(acc[i][j], ah[i], bl[p][2 * jj], bl[p][2 * jj + 1]);
                    mma_bf16(acc[i][j], al[i], bh[p][2 * jj], bh[p][2 * jj + 1]);
                }
            }
        }
        __syncthreads();
    }

    const int mbase = row0 + wm * 64 + (lane >> 2);
    const int nbase = col0 + wn * 32 + (lane & 3) * 2;
#pragma unroll
    for (int i = 0; i < 4; i++) {
#pragma unroll
        for (int j = 0; j < 4; j++) {
            const int r = mbase + i * 16;
            const int c = nbase + j * 8;
            if (SPLIT) {
#pragma unroll
                for (int hrow = 0; hrow < 2; hrow++) {
                    float v0 = acc[i][j][2 * hrow]     * oscale;
                    float v1 = acc[i][j][2 * hrow + 1] * oscale;
                    size_t off = (size_t)(r + 8 * hrow) * N + c;
                    *(uint32_t*)&Ch[off] = pack_hi_trunc(v0, v1);
                    *(uint32_t*)&Cl[off] = packh(resid16(v0), resid16(v1));
                }
            } else {
                *(float2*)&C[(size_t)r * N + c]       = make_float2(acc[i][j][0], acc[i][j][1]);
                *(float2*)&C[(size_t)(r + 8) * N + c] = make_float2(acc[i][j][2], acc[i][j][3]);
            }
        }
    }
}

// ---------------------------------------------------------------------------
// Causal flash attention on mma.sync, split-bf16, FMA-pipe exp2.
// Q pre-scaled by 0.125*log2(e) => S already in log2 domain.
// Br=128 q-rows per CTA (8 warps x 16 rows), Bc=64 kv per tile.
// Launch bounds (256,1) — identical to the round-6 kernel that passed.
// ---------------------------------------------------------------------------
#define FLDS      72                  // padded row stride (bf16), 144 B
#define QBUF_B    (128 * FLDS * 2)    // 18432
#define KVBUF_B   (64 * FLDS * 2)     // 9216
#define KVSTAGE_B (4 * KVBUF_B)       // 36864
#define FLASH_SMEM (2 * QBUF_B + 2 * KVSTAGE_B)   // 110592

__global__ __launch_bounds__(256, 1)
void flash_mma(const __nv_bfloat16* __restrict__ qh_g, const __nv_bfloat16* __restrict__ ql_g,
               const __nv_bfloat16* __restrict__ kh_g, const __nv_bfloat16* __restrict__ kl_g,
               const __nv_bfloat16* __restrict__ vh_g, const __nv_bfloat16* __restrict__ vl_g,
               __nv_bfloat16* __restrict__ ch_g, __nv_bfloat16* __restrict__ cl_g)
{
    extern __shared__ char dsm[];
    const uint32_t smb = smem_u32(dsm);
    const uint32_t sq  = smb;
    const uint32_t skv = smb + 2 * QBUF_B;

    const int tid  = threadIdx.x;
    const int lane = tid & 31;
    const int wid  = tid >> 5;
    const int qb   = blockIdx.x;           // 0..15
    const int b    = blockIdx.y >> 4;
    const int h    = blockIdx.y & 15;
    const int q0   = qb * 128;
    const size_t gbase = (size_t)b * SEQ * DM + h * HD;

    const int ar = lane & 7, asub = lane >> 3;
    const uint32_t aoff = (uint32_t)(((asub & 1) * 8 + ar) * FLDS + (asub >> 1) * 8);
    const uint32_t boff = (uint32_t)(((asub >> 1) * 8 + ar) * FLDS + (asub & 1) * 8);

    const __nv_bfloat16* kvsrc[4] = {kh_g, kl_g, vh_g, vl_g};

    // ---- kv tile 0 prefetch + Q load ----
    {
#pragma unroll
        for (int kk = 0; kk < 8; kk++) {
            int id = tid + kk * 256;
            int buf = id >> 9, row = (id >> 3) & 63, cc = id & 7;
            CP_ASYNC16(skv + buf * KVBUF_B + row * 144 + cc * 16,
                       kvsrc[buf] + gbase + (size_t)row * DM + cc * 8);
        }
        CP_COMMIT();
#pragma unroll
        for (int kk = 0; kk < 8; kk++) {
            int id = tid + kk * 256;
            int buf = id >> 10, row = (id >> 3) & 127, cc = id & 7;
            const __nv_bfloat16* src = (buf ? ql_g : qh_g) + gbase +
                                       (size_t)(q0 + row) * DM + cc * 8;
            CP_ASYNC16(sq + buf * QBUF_B + row * 144 + cc * 16, src);
        }
        CP_COMMIT();
        CP_WAIT(0);
        __syncthreads();
    }

    uint32_t qhf[4][4], qlf[4][4];
#pragma unroll
    for (int kc = 0; kc < 4; kc++) {
        uint32_t o = (aoff + (uint32_t)(wid * 16 * FLDS + kc * 16)) * 2;
        ldmx4(qhf[kc], sq + o);
        ldmx4(qlf[kc], sq + QBUF_B + o);
    }

    float acc[8][4];
#pragma unroll
    for (int f = 0; f < 8; f++)
#pragma unroll
        for (int r = 0; r < 4; r++) acc[f][r] = 0.0f;
    float m0 = -1e30f, m1 = -1e30f, l0 = 0.0f, l1 = 0.0f;

    const int T  = 2 * qb + 2;
    const int rr = lane >> 2, qx = lane & 3;
    const int rowg0 = q0 + wid * 16 + rr;

#pragma unroll 1
    for (int t = 0; t < T; t++) {
        if (t + 1 < T) {
            const uint32_t sb = skv + ((t + 1) & 1) * KVSTAGE_B;
            const int s1 = (t + 1) * 64;
#pragma unroll
            for (int kk = 0; kk < 8; kk++) {
                int id = tid + kk * 256;
                int buf = id >> 9, row = (id >> 3) & 63, cc = id & 7;
                CP_ASYNC16(sb + buf * KVBUF_B + row * 144 + cc * 16,
                           kvsrc[buf] + gbase + (size_t)(s1 + row) * DM + cc * 8);
            }
            CP_COMMIT();
            CP_WAIT(1);
        } else {
            CP_WAIT(0);
        }
        __syncthreads();

        const uint32_t st = skv + (t & 1) * KVSTAGE_B;

        // ---- S = Q K^T (split, 3 passes) ----
        float s[8][4];
#pragma unroll
        for (int f = 0; f < 8; f++)
#pragma unroll
            for (int r = 0; r < 4; r++) s[f][r] = 0.0f;

#pragma unroll
        for (int kc = 0; kc < 4; kc++) {
#pragma unroll
            for (int p = 0; p < 4; p++) {
                uint32_t o = (boff + (uint32_t)(p * 16 * FLDS + kc * 16)) * 2;
                uint32_t kbh[4], kbl[4];
                ldmx4(kbh, st + o);
                ldmx4(kbl, st + KVBUF_B + o);
                mma_bf16(s[2 * p],     qhf[kc], kbh[0], kbh[1]);
                mma_bf16(s[2 * p + 1], qhf[kc], kbh[2], kbh[3]);
                mma_bf16(s[2 * p],     qhf[kc], kbl[0], kbl[1]);
                mma_bf16(s[2 * p + 1], qhf[kc], kbl[2], kbl[3]);
                mma_bf16(s[2 * p],     qlf[kc], kbh[0], kbh[1]);
                mma_bf16(s[2 * p + 1], qlf[kc], kbh[2], kbh[3]);
            }
        }

        // ---- causal mask (diagonal tiles only) ----
        const int s0 = t * 64;
        if (s0 + 63 > q0) {
#pragma unroll
            for (int f = 0; f < 8; f++) {
                int c0 = s0 + f * 8 + 2 * qx;
                if (c0 > rowg0)         s[f][0] = -1e30f;
                if (c0 + 1 > rowg0)     s[f][1] = -1e30f;
                if (c0 > rowg0 + 8)     s[f][2] = -1e30f;
                if (c0 + 1 > rowg0 + 8) s[f][3] = -1e30f;
            }
        }

        // ---- online softmax in log2 domain (quad shfl reductions) ----
        {
            float mx = -1e30f;
#pragma unroll
            for (int f = 0; f < 8; f++) mx = fmaxf(mx, fmaxf(s[f][0], s[f][1]));
            mx = fmaxf(mx, __shfl_xor_sync(0xffffffffu, mx, 1));
            mx = fmaxf(mx, __shfl_xor_sync(0xffffffffu, mx, 2));
            float mn = fmaxf(m0, mx);
            float al = fexp2_raw(m0 - mn);
            m0 = mn;
            float sum = 0.0f;
#pragma unroll
            for (int f = 0; f < 8; f++) {
                s[f][0] = fexp2_raw(s[f][0] - mn);
                s[f][1] = fexp2_raw(s[f][1] - mn);
                sum += s[f][0] + s[f][1];
            }
            sum += __shfl_xor_sync(0xffffffffu, sum, 1);
            sum += __shfl_xor_sync(0xffffffffu, sum, 2);
            l0 = l0 * al + sum;
#pragma unroll
            for (int f = 0; f < 8; f++) { acc[f][0] *= al; acc[f][1] *= al; }
        }
        {
            float mx = -1e30f;
#pragma unroll
            for (int f = 0; f < 8; f++) mx = fmaxf(mx, fmaxf(s[f][2], s[f][3]));
            mx = fmaxf(mx, __shfl_xor_sync(0xffffffffu, mx, 1));
            mx = fmaxf(mx, __shfl_xor_sync(0xffffffffu, mx, 2));
            float mn = fmaxf(m1, mx);
            float al = fexp2_raw(m1 - mn);
            m1 = mn;
            float sum = 0.0f;
#pragma unroll
            for (int f = 0; f < 8; f++) {
                s[f][2] = fexp2_raw(s[f][2] - mn);
                s[f][3] = fexp2_raw(s[f][3] - mn);
                sum += s[f][2] + s[f][3];
            }
            sum += __shfl_xor_sync(0xffffffffu, sum, 1);
            sum += __shfl_xor_sync(0xffffffffu, sum, 2);
            l1 = l1 * al + sum;
#pragma unroll
            for (int f = 0; f < 8; f++) { acc[f][2] *= al; acc[f][3] *= al; }
        }

        // ---- O += P V (split, 3 passes; P stays in registers) ----
#pragma unroll
        for (int jc = 0; jc < 4; jc++) {
            const float* sA = s[2 * jc];
            const float* sB = s[2 * jc + 1];
            uint32_t pha[4], pla[4];
            pha[0] = pack_hi_trunc(sA[0], sA[1]);
            pha[1] = pack_hi_trunc(sA[2], sA[3]);
            pha[2] = pack_hi_trunc(sB[0], sB[1]);
            pha[3] = pack_hi_trunc(sB[2], sB[3]);
            pla[0] = packh(resid16(sA[0]), resid16(sA[1]));
            pla[1] = packh(resid16(sA[2]), resid16(sA[3]));
            pla[2] = packh(resid16(sB[0]), resid16(sB[1]));
            pla[3] = packh(resid16(sB[2]), resid16(sB[3]));
#pragma unroll
            for (int pe = 0; pe < 4; pe++) {
                uint32_t o = (aoff + (uint32_t)(jc * 16 * FLDS + pe * 16)) * 2;
                uint32_t vbh[4], vbl[4];
                ldmx4t(vbh, st + 2 * KVBUF_B + o);
                ldmx4t(vbl, st + 3 * KVBUF_B + o);
                mma_bf16(acc[2 * pe],     pha, vbh[0], vbh[1]);
                mma_bf16(acc[2 * pe + 1], pha, vbh[2], vbh[3]);
                mma_bf16(acc[2 * pe],     pha, vbl[0], vbl[1]);
                mma_bf16(acc[2 * pe + 1], pha, vbl[2], vbl[3]);
                mma_bf16(acc[2 * pe],     pla, vbh[0], vbh[1]);
                mma_bf16(acc[2 * pe + 1], pla, vbh[2], vbh[3]);
            }
        }
        __syncthreads();
    }

    // ---- epilogue: normalize, trunc-split to bf16 hi/lo, store ----
    const float inv0 = 1.0f / l0;
    const float inv1 = 1.0f / l1;
#pragma unroll
    for (int f = 0; f < 8; f++) {
        const int coloff = f * 8 + 2 * qx;
#pragma unroll
        for (int hrow = 0; hrow < 2; hrow++) {
            float inv = hrow ? inv1 : inv0;
            float v0 = acc[f][2 * hrow]     * inv;
            float v1 = acc[f][2 * hrow + 1] * inv;
            size_t off = gbase + (size_t)(rowg0 + 8 * hrow) * DM + coloff;
            *(uint32_t*)&ch_g[off] = pack_hi_trunc(v0, v1);
            *(uint32_t*)&cl_g[off] = packh(resid16(v0), resid16(v1));
        }
    }
}

// ---------------------------------------------------------------------------
extern "C" void kernel_launch(void* const* d_in, const int* in_sizes, int n_in,
                              void* d_out, int out_size)
{
    const float* x  = (const float*)d_in[0];
    const float* Wq = (const float*)d_in[1];
    const float* Wk = (const float*)d_in[2];
    const float* Wv = (const float*)d_in[3];
    const float* Wo = (const float*)d_in[4];
    float* out = (float*)d_out;

    __nv_bfloat16 *xh, *xl, *qh, *ql, *kh, *kl, *vh, *vl, *ch, *cl;
    __nv_bfloat16 *wqh, *wql, *wkh, *wkl, *wvh, *wvl, *woh, *wol;
    cudaGetSymbolAddress((void**)&xh, g_xh);
    cudaGetSymbolAddress((void**)&xl, g_xl);
    cudaGetSymbolAddress((void**)&qh, g_qh);
    cudaGetSymbolAddress((void**)&ql, g_ql);
    cudaGetSymbolAddress((void**)&kh, g_kh);
    cudaGetSymbolAddress((void**)&kl, g_kl);
    cudaGetSymbolAddress((void**)&vh, g_vh);
    cudaGetSymbolAddress((void**)&vl, g_vl);
    cudaGetSymbolAddress((void**)&ch, g_ch);
    cudaGetSymbolAddress((void**)&cl, g_cl);
    cudaGetSymbolAddress((void**)&wqh, g_wqh);
    cudaGetSymbolAddress((void**)&wql, g_wql);
    cudaGetSymbolAddress((void**)&wkh, g_wkh);
    cudaGetSymbolAddress((void**)&wkl, g_wkl);
    cudaGetSymbolAddress((void**)&wvh, g_wvh);
    cudaGetSymbolAddress((void**)&wvl, g_wvl);
    cudaGetSymbolAddress((void**)&woh, g_woh);
    cudaGetSymbolAddress((void**)&wol, g_wol);

    cudaFuncSetAttribute(gemm_mma<0>,
                         cudaFuncAttributeMaxDynamicSharedMemorySize, GEMM_SMEM);
    cudaFuncSetAttribute(gemm_mma<1>,
                         cudaFuncAttributeMaxDynamicSharedMemorySize, GEMM_SMEM);
    cudaFuncSetAttribute(flash_mma,
                         cudaFuncAttributeMaxDynamicSharedMemorySize, FLASH_SMEM);

    const int M  = BATCH * SEQ;           // 8192
    const int n4x = M * DM / 4;
    const int n4w = DM * DM / 4;

    // fp32 -> bf16 hi/lo splits (input + weights only)
    split_f32<<<n4x / 256, 256>>>(x, xh, xl, n4x);
    split_f32<<<n4w / 256, 256>>>(Wq, wqh, wql, n4w);
    split_f32<<<n4w / 256, 256>>>(Wk, wkh, wkl, n4w);
    split_f32<<<n4w / 256, 256>>>(Wv, wvh, wvl, n4w);
    split_f32<<<n4w / 256, 256>>>(Wo, woh, wol, n4w);

    // QKV projections -> split bf16 outputs directly (Q pre-scaled to log2 domain)
    dim3 gproj(DM / 128, M / 128);
    gemm_mma<1><<<gproj, 256, GEMM_SMEM>>>(xh, xl, wqh, wql, nullptr, qh, ql, QSCALE, M, DM, DM);
    gemm_mma<1><<<gproj, 256, GEMM_SMEM>>>(xh, xl, wkh, wkl, nullptr, kh, kl, 1.0f, M, DM, DM);
    gemm_mma<1><<<gproj, 256, GEMM_SMEM>>>(xh, xl, wvh, wvl, nullptr, vh, vl, 1.0f, M, DM, DM);

    // causal attention on tensor cores -> split ctx
    flash_mma<<<dim3(SEQ / 128, BATCH * NH), 256, FLASH_SMEM>>>(
        qh, ql, kh, kl, vh, vl, ch, cl);

    // output projection (fp32 out)
    gemm_mma<0><<<gproj, 256, GEMM_SMEM>>>(ch, cl, woh, wol, out, nullptr, nullptr, 1.0f, M, DM, DM);
}

// round 10
// speedup vs baseline: 2.4359x; 1.0106x over previous
#include <cuda_runtime.h>
#include <cuda_bf16.h>
#include <cstdint>

#define SEQ   2048
#define BATCH 4
#define NH    16
#define DM    1024
#define HD    64

// ---------------------------------------------------------------------------
// Scratch (__device__ globals; no allocation allowed anywhere)
// ---------------------------------------------------------------------------
__device__ __align__(256) __nv_bfloat16 g_xh[BATCH * SEQ * DM];
__device__ __align__(256) __nv_bfloat16 g_xl[BATCH * SEQ * DM];
__device__ __align__(256) __nv_bfloat16 g_qh[BATCH * SEQ * DM];
__device__ __align__(256) __nv_bfloat16 g_ql[BATCH * SEQ * DM];
__device__ __align__(256) __nv_bfloat16 g_kh[BATCH * SEQ * DM];
__device__ __align__(256) __nv_bfloat16 g_kl[BATCH * SEQ * DM];
__device__ __align__(256) __nv_bfloat16 g_vh[BATCH * SEQ * DM];
__device__ __align__(256) __nv_bfloat16 g_vl[BATCH * SEQ * DM];
__device__ __align__(256) __nv_bfloat16 g_ch[BATCH * SEQ * DM];
__device__ __align__(256) __nv_bfloat16 g_cl[BATCH * SEQ * DM];
__device__ __align__(256) __nv_bfloat16 g_wqh[DM * DM];
__device__ __align__(256) __nv_bfloat16 g_wql[DM * DM];
__device__ __align__(256) __nv_bfloat16 g_wkh[DM * DM];
__device__ __align__(256) __nv_bfloat16 g_wkl[DM * DM];
__device__ __align__(256) __nv_bfloat16 g_wvh[DM * DM];
__device__ __align__(256) __nv_bfloat16 g_wvl[DM * DM];
__device__ __align__(256) __nv_bfloat16 g_woh[DM * DM];
__device__ __align__(256) __nv_bfloat16 g_wol[DM * DM];

// Q pre-scale: 0.125 * log2(e) — S arrives in log2 domain
#define QSCALE 0.18033688011112042f

// ---------------------------------------------------------------------------
// Baseline-PTX helpers (mma.sync / ldmatrix / cp.async — legal on sm_100)
// ---------------------------------------------------------------------------
__device__ __forceinline__ uint32_t smem_u32(const void* p) {
    uint32_t a;
    asm("{ .reg .u64 t; cvta.to.shared.u64 t, %1; cvt.u32.u64 %0, t; }"
        : "=r"(a) : "l"(p));
    return a;
}

__device__ __forceinline__ void ldmx4(uint32_t* r, uint32_t addr) {
    asm volatile("ldmatrix.sync.aligned.m8n8.x4.shared.b16 {%0,%1,%2,%3}, [%4];"
                 : "=r"(r[0]), "=r"(r[1]), "=r"(r[2]), "=r"(r[3]) : "r"(addr));
}

__device__ __forceinline__ void ldmx4t(uint32_t* r, uint32_t addr) {
    asm volatile("ldmatrix.sync.aligned.m8n8.x4.trans.shared.b16 {%0,%1,%2,%3}, [%4];"
                 : "=r"(r[0]), "=r"(r[1]), "=r"(r[2]), "=r"(r[3]) : "r"(addr));
}

__device__ __forceinline__ void mma_bf16(float* c, const uint32_t* a,
                                         uint32_t b0, uint32_t b1) {
    asm volatile(
        "mma.sync.aligned.m16n8k16.row.col.f32.bf16.bf16.f32 "
        "{%0,%1,%2,%3}, {%4,%5,%6,%7}, {%8,%9}, {%0,%1,%2,%3};"
        : "+f"(c[0]), "+f"(c[1]), "+f"(c[2]), "+f"(c[3])
        : "r"(a[0]), "r"(a[1]), "r"(a[2]), "r"(a[3]), "r"(b0), "r"(b1));
}

#define CP_ASYNC16(dst, src) \
    asm volatile("cp.async.cg.shared.global [%0], [%1], 16;" \
                 :: "r"(dst), "l"(src) : "memory")
#define CP_COMMIT()  asm volatile("cp.async.commit_group;" ::: "memory")
#define CP_WAIT(n)   asm volatile("cp.async.wait_group %0;" :: "n"(n) : "memory")
#define BAR_SYNC(id, cnt) \
    asm volatile("bar.sync %0, %1;" :: "r"(id), "r"(cnt) : "memory")

// pack two fp32 into bf16x2 reg (rn; intrinsic, arch-safe)
__device__ __forceinline__ uint32_t packh(float lo, float hi) {
    __nv_bfloat162 t = __floats2bfloat162_rn(lo, hi);
    return *(uint32_t*)&t;
}

// PRMT trunc-split helpers: hi pair = high halves of two fp32 (1 ALU op);
// residual = v - trunc16(v), exact in fp32.
__device__ __forceinline__ uint32_t pack_hi_trunc(float a, float b) {
    return __byte_perm(__float_as_uint(a), __float_as_uint(b), 0x7632);
}
__device__ __forceinline__ float resid16(float v) {
    return v - __uint_as_float(__float_as_uint(v) & 0xffff0000u);
}

// exp2(d) for d <= 0, deg-5 poly on r in [-0.5, 0.5]. FMA-pipe only.
__device__ __forceinline__ float fexp2_raw(float d) {
    float t = fmaxf(d, -115.0f);
    int   e = __float2int_rn(t);
    float r = t - (float)e;
    float p = 1.3333558146e-3f;
    p = fmaf(p, r, 9.6181291076e-3f);
    p = fmaf(p, r, 5.5504108665e-2f);
    p = fmaf(p, r, 2.4022650696e-1f);
    p = fmaf(p, r, 6.9314718056e-1f);
    p = fmaf(p, r, 1.0f);
    return __int_as_float(__float_as_int(p) + (e << 23));
}

// ---------------------------------------------------------------------------
// fp32 -> (hi, lo) bf16 trunc-split, vectorized by 4
// ---------------------------------------------------------------------------
__global__ void split_f32(const float* __restrict__ in,
                          __nv_bfloat16* __restrict__ hi,
                          __nv_bfloat16* __restrict__ lo, int n4)
{
    int i = blockIdx.x * blockDim.x + threadIdx.x;
    if (i >= n4) return;
    float4 v = ((const float4*)in)[i];
    uint32_t* hp = (uint32_t*)hi;
    uint32_t* lp = (uint32_t*)lo;
    hp[2 * i]     = pack_hi_trunc(v.x, v.y);
    hp[2 * i + 1] = pack_hi_trunc(v.z, v.w);
    lp[2 * i]     = packh(resid16(v.x), resid16(v.y));
    lp[2 * i + 1] = packh(resid16(v.z), resid16(v.w));
}

// ---------------------------------------------------------------------------
// GEMM tile machinery shared by gemm_qkv / gemm_out.
// 128x128 CTA tile, BK=32, 8 warps (2x4), warp tile 64x32, m16n8k16.
// ---------------------------------------------------------------------------
#define LDS       40
#define TILE_E    (128 * LDS)
#define TILE_B2   (TILE_E * 2)
#define STAGE_B2  (4 * TILE_B2)
#define GEMM_SMEM (2 * STAGE_B2)

// body macro-free: both kernels share this inline function for the mainloop.
struct GemmCtx {
    uint32_t smb, d0, d1, aoff, boff;
    int tid, lane, wid, wm, wn;
    int r0c, c0c, r1c, c1c;
};

__device__ __forceinline__ void gemm_mainloop(
    const GemmCtx& cx,
    const __nv_bfloat16* const* gsrc, float acc[4][4][4])
{
    const int K = DM;
    const int KSTAGES = K / 32;
    {
        const uint32_t sb = cx.smb;
#pragma unroll
        for (int t = 0; t < 4; t++) {
            const __nv_bfloat16* g = gsrc[t];
            CP_ASYNC16(sb + t * TILE_B2 + cx.d0, g + (size_t)cx.r0c * K + cx.c0c * 8);
            CP_ASYNC16(sb + t * TILE_B2 + cx.d1, g + (size_t)cx.r1c * K + cx.c1c * 8);
        }
        CP_COMMIT();
    }
#pragma unroll 1
    for (int kt = 0; kt < KSTAGES; kt++) {
        if (kt + 1 < KSTAGES) {
            const uint32_t sb = cx.smb + ((kt + 1) & 1) * STAGE_B2;
            const int kk = (kt + 1) * 32;
#pragma unroll
            for (int t = 0; t < 4; t++) {
                const __nv_bfloat16* g = gsrc[t];
                CP_ASYNC16(sb + t * TILE_B2 + cx.d0, g + (size_t)cx.r0c * K + kk + cx.c0c * 8);
                CP_ASYNC16(sb + t * TILE_B2 + cx.d1, g + (size_t)cx.r1c * K + kk + cx.c1c * 8);
            }
            CP_COMMIT();
            CP_WAIT(1);
        } else {
            CP_WAIT(0);
        }
        __syncthreads();

        const uint32_t sb  = cx.smb + (kt & 1) * STAGE_B2;
        const uint32_t sAh = sb;
        const uint32_t sAl = sb + TILE_B2;
        const uint32_t sBh = sb + 2 * TILE_B2;
        const uint32_t sBl = sb + 3 * TILE_B2;

#pragma unroll
        for (int ks = 0; ks < 2; ks++) {
            uint32_t ah[4][4], al[4][4], bh[2][4], bl[2][4];
#pragma unroll
            for (int i = 0; i < 4; i++) {
                uint32_t o = (cx.aoff + (uint32_t)((cx.wm * 64 + i * 16) * LDS + ks * 16)) * 2;
                ldmx4(ah[i], sAh + o);
                ldmx4(al[i], sAl + o);
            }
#pragma unroll
            for (int p = 0; p < 2; p++) {
                uint32_t o = (cx.boff + (uint32_t)((cx.wn * 32 + p * 16) * LDS + ks * 16)) * 2;
                ldmx4(bh[p], sBh + o);
                ldmx4(bl[p], sBl + o);
            }
#pragma unroll
            for (int i = 0; i < 4; i++) {
#pragma unroll
                for (int j = 0; j < 4; j++) {
                    const int p = j >> 1, jj = j & 1;
                    mma_bf16(acc[i][j], ah[i], bh[p][2 * jj], bh[p][2 * jj + 1]);
                    mma_bf16(acc[i][j], ah[i], bl[p][2 * jj], bl[p][2 * jj + 1]);
                    mma_bf16(acc[i][j], al[i], bh[p][2 * jj], bh[p][2 * jj + 1]);
                }
            }
        }
        __syncthreads();
    }
}

__device__ __forceinline__ GemmCtx make_ctx(uint32_t smb) {
    GemmCtx cx;
    cx.smb = smb;
    cx.tid = threadIdx.x;
    cx.lane = cx.tid & 31;
    cx.wid = cx.tid >> 5;
    cx.wm = cx.wid & 1;
    cx.wn = cx.wid >> 1;
    const int ch0 = cx.tid, ch1 = cx.tid + 256;
    cx.r0c = ch0 >> 2; cx.c0c = ch0 & 3;
    cx.r1c = ch1 >> 2; cx.c1c = ch1 & 3;
    cx.d0 = (uint32_t)(cx.r0c * LDS + cx.c0c * 8) * 2;
    cx.d1 = (uint32_t)(cx.r1c * LDS + cx.c1c * 8) * 2;
    const int aq = cx.lane >> 3, ar = cx.lane & 7;
    cx.aoff = (uint32_t)(((aq & 1) * 8 + ar) * LDS + (aq >> 1) * 8);
    cx.boff = (uint32_t)(((aq >> 1) * 8 + ar) * LDS + (aq & 1) * 8);
    return cx;
}

// QKV fused: gridDim.z in {0,1,2} selects weight/output set; split epilogue.
__global__ __launch_bounds__(256, 1)
void gemm_qkv(const __nv_bfloat16* __restrict__ Ah, const __nv_bfloat16* __restrict__ Al,
              const __nv_bfloat16* __restrict__ Bqh, const __nv_bfloat16* __restrict__ Bql,
              const __nv_bfloat16* __restrict__ Bkh, const __nv_bfloat16* __restrict__ Bkl,
              const __nv_bfloat16* __restrict__ Bvh, const __nv_bfloat16* __restrict__ Bvl,
              __nv_bfloat16* __restrict__ Cqh, __nv_bfloat16* __restrict__ Cql,
              __nv_bfloat16* __restrict__ Ckh, __nv_bfloat16* __restrict__ Ckl,
              __nv_bfloat16* __restrict__ Cvh, __nv_bfloat16* __restrict__ Cvl)
{
    extern __shared__ char dsm[];
    GemmCtx cx = make_ctx(smem_u32(dsm));

    const __nv_bfloat16 *Bh, *Bl;
    __nv_bfloat16 *Ch, *Cl;
    float oscale;
    if (blockIdx.z == 0)      { Bh = Bqh; Bl = Bql; Ch = Cqh; Cl = Cql; oscale = QSCALE; }
    else if (blockIdx.z == 1) { Bh = Bkh; Bl = Bkl; Ch = Ckh; Cl = Ckl; oscale = 1.0f; }
    else                      { Bh = Bvh; Bl = Bvl; Ch = Cvh; Cl = Cvl; oscale = 1.0f; }

    const int row0 = blockIdx.y * 128;
    const int col0 = blockIdx.x * 128;
    const __nv_bfloat16* gsrc[4] = {
        Ah + (size_t)row0 * DM, Al + (size_t)row0 * DM,
        Bh + (size_t)col0 * DM, Bl + (size_t)col0 * DM
    };

    float acc[4][4][4];
#pragma unroll
    for (int i = 0; i < 4; i++)
#pragma unroll
        for (int j = 0; j < 4; j++)
#pragma unroll
            for (int r = 0; r < 4; r++) acc[i][j][r] = 0.0f;

    gemm_mainloop(cx, gsrc, acc);

    const int mbase = row0 + cx.wm * 64 + (cx.lane >> 2);
    const int nbase = col0 + cx.wn * 32 + (cx.lane & 3) * 2;
#pragma unroll
    for (int i = 0; i < 4; i++) {
#pragma unroll
        for (int j = 0; j < 4; j++) {
            const int r = mbase + i * 16;
            const int c = nbase + j * 8;
#pragma unroll
            for (int hrow = 0; hrow < 2; hrow++) {
                float v0 = acc[i][j][2 * hrow]     * oscale;
                float v1 = acc[i][j][2 * hrow + 1] * oscale;
                size_t off = (size_t)(r + 8 * hrow) * DM + c;
                *(uint32_t*)&Ch[off] = pack_hi_trunc(v0, v1);
                *(uint32_t*)&Cl[off] = packh(resid16(v0), resid16(v1));
            }
        }
    }
}

// Output projection: fp32 epilogue.
__global__ __launch_bounds__(256, 1)
void gemm_out(const __nv_bfloat16* __restrict__ Ah, const __nv_bfloat16* __restrict__ Al,
              const __nv_bfloat16* __restrict__ Bh, const __nv_bfloat16* __restrict__ Bl,
              float* __restrict__ C)
{
    extern __shared__ char dsm[];
    GemmCtx cx = make_ctx(smem_u32(dsm));

    const int row0 = blockIdx.y * 128;
    const int col0 = blockIdx.x * 128;
    const __nv_bfloat16* gsrc[4] = {
        Ah + (size_t)row0 * DM, Al + (size_t)row0 * DM,
        Bh + (size_t)col0 * DM, Bl + (size_t)col0 * DM
    };

    float acc[4][4][4];
#pragma unroll
    for (int i = 0; i < 4; i++)
#pragma unroll
        for (int j = 0; j < 4; j++)
#pragma unroll
            for (int r = 0; r < 4; r++) acc[i][j][r] = 0.0f;

    gemm_mainloop(cx, gsrc, acc);

    const int mbase = row0 + cx.wm * 64 + (cx.lane >> 2);
    const int nbase = col0 + cx.wn * 32 + (cx.lane & 3) * 2;
#pragma unroll
    for (int i = 0; i < 4; i++) {
#pragma unroll
        for (int j = 0; j < 4; j++) {
            const int r = mbase + i * 16;
            const int c = nbase + j * 8;
            *(float2*)&C[(size_t)r * DM + c]       = make_float2(acc[i][j][0], acc[i][j][1]);
            *(float2*)&C[(size_t)(r + 8) * DM + c] = make_float2(acc[i][j][2], acc[i][j][3]);
        }
    }
}

// ---------------------------------------------------------------------------
// Causal flash attention on mma.sync, split-bf16, FMA-pipe exp2.
// Br=128 per CTA, TWO INDEPENDENT 4-warp GROUPS (rows 0-63 / 64-127), each
// with its own KV double buffer + named barrier -> groups drift out of phase
// so one group's softmax overlaps the other's tensor work on each SMSP.
// ---------------------------------------------------------------------------
#define FLDS      72                  // padded row stride (bf16), 144 B
#define QBUF_B    (128 * FLDS * 2)    // 18432
#define KVBUF_B   (64 * FLDS * 2)     // 9216
#define KVSTAGE_B (4 * KVBUF_B)       // 36864 (kh,kl,vh,vl)
#define KVGRP_B   (2 * KVSTAGE_B)     // per-group double buffer
#define FLASH_SMEM (2 * QBUF_B + 2 * KVGRP_B)   // 184320

__global__ __launch_bounds__(256, 1)
void flash_mma(const __nv_bfloat16* __restrict__ qh_g, const __nv_bfloat16* __restrict__ ql_g,
               const __nv_bfloat16* __restrict__ kh_g, const __nv_bfloat16* __restrict__ kl_g,
               const __nv_bfloat16* __restrict__ vh_g, const __nv_bfloat16* __restrict__ vl_g,
               __nv_bfloat16* __restrict__ ch_g, __nv_bfloat16* __restrict__ cl_g)
{
    extern __shared__ char dsm[];
    const uint32_t smb = smem_u32(dsm);
    const uint32_t sq  = smb;
    const uint32_t skv = smb + 2 * QBUF_B;

    const int tid  = threadIdx.x;
    const int lane = tid & 31;
    const int wid  = tid >> 5;
    const int g      = wid >> 2;          // group 0/1
    const int wg_tid = tid & 127;
    const uint32_t skvg = skv + (uint32_t)g * KVGRP_B;

    const int qb   = (int)(gridDim.x - 1 - blockIdx.x);   // longest-first
    const int b    = blockIdx.y >> 4;
    const int h    = blockIdx.y & 15;
    const int q0   = qb * 128;
    const size_t gbase = (size_t)b * SEQ * DM + h * HD;

    const int ar = lane & 7, asub = lane >> 3;
    const uint32_t aoff = (uint32_t)(((asub & 1) * 8 + ar) * FLDS + (asub >> 1) * 8);
    const uint32_t boff = (uint32_t)(((asub >> 1) * 8 + ar) * FLDS + (asub & 1) * 8);

    const __nv_bfloat16* kvsrc[4] = {kh_g, kl_g, vh_g, vl_g};

    // ---- group prefetch of kv tile 0 + shared Q load ----
    {
#pragma unroll
        for (int kk = 0; kk < 16; kk++) {
            int id = wg_tid + kk * 128;          // 0..2047
            int buf = id >> 9, row = (id >> 3) & 63, cc = id & 7;
            CP_ASYNC16(skvg + buf * KVBUF_B + row * 144 + cc * 16,
                       kvsrc[buf] + gbase + (size_t)row * DM + cc * 8);
        }
        CP_COMMIT();
#pragma unroll
        for (int kk = 0; kk < 8; kk++) {
            int id = tid + kk * 256;
            int buf = id >> 10, row = (id >> 3) & 127, cc = id & 7;
            const __nv_bfloat16* src = (buf ? ql_g : qh_g) + gbase +
                                       (size_t)(q0 + row) * DM + cc * 8;
            CP_ASYNC16(sq + buf * QBUF_B + row * 144 + cc * 16, src);
        }
        CP_COMMIT();
        CP_WAIT(0);
        __syncthreads();
    }

    uint32_t qhf[4][4], qlf[4][4];
#pragma unroll
    for (int kc = 0; kc < 4; kc++) {
        uint32_t o = (aoff + (uint32_t)(wid * 16 * FLDS + kc * 16)) * 2;
        ldmx4(qhf[kc], sq + o);
        ldmx4(qlf[kc], sq + QBUF_B + o);
    }

    float acc[8][4];
#pragma unroll
    for (int f = 0; f < 8; f++)
#pragma unroll
        for (int r = 0; r < 4; r++) acc[f][r] = 0.0f;
    float m0 = -1e30f, m1 = -1e30f, l0 = 0.0f, l1 = 0.0f;

    const int T  = 2 * qb + 1 + g;        // group causal extent
    const int rr = lane >> 2, qx = lane & 3;
    const int rowg0 = q0 + wid * 16 + rr;
    const int gmin  = q0 + 64 * g;        // group's lowest q row

#pragma unroll 1
    for (int t = 0; t < T; t++) {
        // tile t data was committed last iteration (or pre-loop)
        CP_WAIT(0);
        BAR_SYNC(1 + g, 128);
        if (t + 1 < T) {
            const uint32_t sb = skvg + ((t + 1) & 1) * KVSTAGE_B;
            const int s1 = (t + 1) * 64;
#pragma unroll
            for (int kk = 0; kk < 16; kk++) {
                int id = wg_tid + kk * 128;
                int buf = id >> 9, row = (id >> 3) & 63, cc = id & 7;
                CP_ASYNC16(sb + buf * KVBUF_B + row * 144 + cc * 16,
                           kvsrc[buf] + gbase + (size_t)(s1 + row) * DM + cc * 8);
            }
            CP_COMMIT();
        }

        const uint32_t st = skvg + (t & 1) * KVSTAGE_B;

        // ---- S = Q K^T (split, 3 passes) ----
        float s[8][4];
#pragma unroll
        for (int f = 0; f < 8; f++)
#pragma unroll
            for (int r = 0; r < 4; r++) s[f][r] = 0.0f;

#pragma unroll
        for (int kc = 0; kc < 4; kc++) {
#pragma unroll
            for (int p = 0; p < 4; p++) {
                uint32_t o = (boff + (uint32_t)(p * 16 * FLDS + kc * 16)) * 2;
                uint32_t kbh[4], kbl[4];
                ldmx4(kbh, st + o);
                ldmx4(kbl, st + KVBUF_B + o);
                mma_bf16(s[2 * p],     qhf[kc], kbh[0], kbh[1]);
                mma_bf16(s[2 * p + 1], qhf[kc], kbh[2], kbh[3]);
                mma_bf16(s[2 * p],     qhf[kc], kbl[0], kbl[1]);
                mma_bf16(s[2 * p + 1], qhf[kc], kbl[2], kbl[3]);
                mma_bf16(s[2 * p],     qlf[kc], kbh[0], kbh[1]);
                mma_bf16(s[2 * p + 1], qlf[kc], kbh[2], kbh[3]);
            }
        }

        // ---- causal mask (diagonal tiles of THIS group only) ----
        const int s0 = t * 64;
        if (s0 + 63 > gmin) {
#pragma unroll
            for (int f = 0; f < 8; f++) {
                int c0 = s0 + f * 8 + 2 * qx;
                if (c0 > rowg0)         s[f][0] = -1e30f;
                if (c0 + 1 > rowg0)     s[f][1] = -1e30f;
                if (c0 > rowg0 + 8)     s[f][2] = -1e30f;
                if (c0 + 1 > rowg0 + 8) s[f][3] = -1e30f;
            }
        }

        // ---- online softmax in log2 domain (quad shfl reductions) ----
        {
            float mx = -1e30f;
#pragma unroll
            for (int f = 0; f < 8; f++) mx = fmaxf(mx, fmaxf(s[f][0], s[f][1]));
            mx = fmaxf(mx, __shfl_xor_sync(0xffffffffu, mx, 1));
            mx = fmaxf(mx, __shfl_xor_sync(0xffffffffu, mx, 2));
            float mn = fmaxf(m0, mx);
            float al = fexp2_raw(m0 - mn);
            m0 = mn;
            float sum = 0.0f;
#pragma unroll
            for (int f = 0; f < 8; f++) {
                s[f][0] = fexp2_raw(s[f][0] - mn);
                s[f][1] = fexp2_raw(s[f][1] - mn);
                sum += s[f][0] + s[f][1];
            }
            sum += __shfl_xor_sync(0xffffffffu, sum, 1);
            sum += __shfl_xor_sync(0xffffffffu, sum, 2);
            l0 = l0 * al + sum;
#pragma unroll
            for (int f = 0; f < 8; f++) { acc[f][0] *= al; acc[f][1] *= al; }
        }
        {
            float mx = -1e30f;
#pragma unroll
            for (int f = 0; f < 8; f++) mx = fmaxf(mx, fmaxf(s[f][2], s[f][3]));
            mx = fmaxf(mx, __shfl_xor_sync(0xffffffffu, mx, 1));
            mx = fmaxf(mx, __shfl_xor_sync(0xffffffffu, mx, 2));
            float mn = fmaxf(m1, mx);
            float al = fexp2_raw(m1 - mn);
            m1 = mn;
            float sum = 0.0f;
#pragma unroll
            for (int f = 0; f < 8; f++) {
                s[f][2] = fexp2_raw(s[f][2] - mn);
                s[f][3] = fexp2_raw(s[f][3] - mn);
                sum += s[f][2] + s[f][3];
            }
            sum += __shfl_xor_sync(0xffffffffu, sum, 1);
            sum += __shfl_xor_sync(0xffffffffu, sum, 2);
            l1 = l1 * al + sum;
#pragma unroll
            for (int f = 0; f < 8; f++) { acc[f][2] *= al; acc[f][3] *= al; }
        }

        // ---- O += P V (split, 3 passes; P stays in registers) ----
#pragma unroll
        for (int jc = 0; jc < 4; jc++) {
            const float* sA = s[2 * jc];
            const float* sB = s[2 * jc + 1];
            uint32_t pha[4], pla[4];
            pha[0] = pack_hi_trunc(sA[0], sA[1]);
            pha[1] = pack_hi_trunc(sA[2], sA[3]);
            pha[2] = pack_hi_trunc(sB[0], sB[1]);
            pha[3] = pack_hi_trunc(sB[2], sB[3]);
            pla[0] = packh(resid16(sA[0]), resid16(sA[1]));
            pla[1] = packh(resid16(sA[2]), resid16(sA[3]));
            pla[2] = packh(resid16(sB[0]), resid16(sB[1]));
            pla[3] = packh(resid16(sB[2]), resid16(sB[3]));
#pragma unroll
            for (int pe = 0; pe < 4; pe++) {
                uint32_t o = (aoff + (uint32_t)(jc * 16 * FLDS + pe * 16)) * 2;
                uint32_t vbh[4], vbl[4];
                ldmx4t(vbh, st + 2 * KVBUF_B + o);
                ldmx4t(vbl, st + 3 * KVBUF_B + o);
                mma_bf16(acc[2 * pe],     pha, vbh[0], vbh[1]);
                mma_bf16(acc[2 * pe + 1], pha, vbh[2], vbh[3]);
                mma_bf16(acc[2 * pe],     pha, vbl[0], vbl[1]);
                mma_bf16(acc[2 * pe + 1], pha, vbl[2], vbl[3]);
                mma_bf16(acc[2 * pe],     pla, vbh[0], vbh[1]);
                mma_bf16(acc[2 * pe + 1], pla, vbh[2], vbh[3]);
            }
        }
    }

    // ---- epilogue: normalize, trunc-split to bf16 hi/lo, store ----
    const float inv0 = 1.0f / l0;
    const float inv1 = 1.0f / l1;
#pragma unroll
    for (int f = 0; f < 8; f++) {
        const int coloff = f * 8 + 2 * qx;
#pragma unroll
        for (int hrow = 0; hrow < 2; hrow++) {
            float inv = hrow ? inv1 : inv0;
            float v0 = acc[f][2 * hrow]     * inv;
            float v1 = acc[f][2 * hrow + 1] * inv;
            size_t off = gbase + (size_t)(rowg0 + 8 * hrow) * DM + coloff;
            *(uint32_t*)&ch_g[off] = pack_hi_trunc(v0, v1);
            *(uint32_t*)&cl_g[off] = packh(resid16(v0), resid16(v1));
        }
    }
}

// ---------------------------------------------------------------------------
extern "C" void kernel_launch(void* const* d_in, const int* in_sizes, int n_in,
                              void* d_out, int out_size)
{
    const float* x  = (const float*)d_in[0];
    const float* Wq = (const float*)d_in[1];
    const float* Wk = (const float*)d_in[2];
    const float* Wv = (const float*)d_in[3];
    const float* Wo = (const float*)d_in[4];
    float* out = (float*)d_out;

    __nv_bfloat16 *xh, *xl, *qh, *ql, *kh, *kl, *vh, *vl, *ch, *cl;
    __nv_bfloat16 *wqh, *wql, *wkh, *wkl, *wvh, *wvl, *woh, *wol;
    cudaGetSymbolAddress((void**)&xh, g_xh);
    cudaGetSymbolAddress((void**)&xl, g_xl);
    cudaGetSymbolAddress((void**)&qh, g_qh);
    cudaGetSymbolAddress((void**)&ql, g_ql);
    cudaGetSymbolAddress((void**)&kh, g_kh);
    cudaGetSymbolAddress((void**)&kl, g_kl);
    cudaGetSymbolAddress((void**)&vh, g_vh);
    cudaGetSymbolAddress((void**)&vl, g_vl);
    cudaGetSymbolAddress((void**)&ch, g_ch);
    cudaGetSymbolAddress((void**)&cl, g_cl);
    cudaGetSymbolAddress((void**)&wqh, g_wqh);
    cudaGetSymbolAddress((void**)&wql, g_wql);
    cudaGetSymbolAddress((void**)&wkh, g_wkh);
    cudaGetSymbolAddress((void**)&wkl, g_wkl);
    cudaGetSymbolAddress((void**)&wvh, g_wvh);
    cudaGetSymbolAddress((void**)&wvl, g_wvl);
    cudaGetSymbolAddress((void**)&woh, g_woh);
    cudaGetSymbolAddress((void**)&wol, g_wol);

    cudaFuncSetAttribute(gemm_qkv,
                         cudaFuncAttributeMaxDynamicSharedMemorySize, GEMM_SMEM);
    cudaFuncSetAttribute(gemm_out,
                         cudaFuncAttributeMaxDynamicSharedMemorySize, GEMM_SMEM);
    cudaFuncSetAttribute(flash_mma,
                         cudaFuncAttributeMaxDynamicSharedMemorySize, FLASH_SMEM);

    const int M  = BATCH * SEQ;           // 8192
    const int n4x = M * DM / 4;
    const int n4w = DM * DM / 4;

    // fp32 -> bf16 hi/lo splits (input + weights only)
    split_f32<<<n4x / 256, 256>>>(x, xh, xl, n4x);
    split_f32<<<n4w / 256, 256>>>(Wq, wqh, wql, n4w);
    split_f32<<<n4w / 256, 256>>>(Wk, wkh, wkl, n4w);
    split_f32<<<n4w / 256, 256>>>(Wv, wvh, wvl, n4w);
    split_f32<<<n4w / 256, 256>>>(Wo, woh, wol, n4w);

    // Fused QKV projections (one launch, z selects weight set; Q pre-scaled)
    dim3 gqkv(DM / 128, M / 128, 3);      // (8, 64, 3) = 1536 CTAs
    gemm_qkv<<<gqkv, 256, GEMM_SMEM>>>(xh, xl,
                                       wqh, wql, wkh, wkl, wvh, wvl,
                                       qh, ql, kh, kl, vh, vl);

    // causal attention on tensor cores -> split ctx
    flash_mma<<<dim3(SEQ / 128, BATCH * NH), 256, FLASH_SMEM>>>(
        qh, ql, kh, kl, vh, vl, ch, cl);

    // output projection (fp32 out)
    gemm_out<<<dim3(DM / 128, M / 128), 256, GEMM_SMEM>>>(ch, cl, woh, wol, out);
}

// round 11
// speedup vs baseline: 2.5642x; 1.0527x over previous
#include <cuda_runtime.h>
#include <cuda_bf16.h>
#include <cstdint>

#define SEQ   2048
#define BATCH 4
#define NH    16
#define DM    1024
#define HD    64

// ---------------------------------------------------------------------------
// Scratch (__device__ globals; no allocation allowed anywhere)
// ---------------------------------------------------------------------------
__device__ __align__(256) __nv_bfloat16 g_xh[BATCH * SEQ * DM];
__device__ __align__(256) __nv_bfloat16 g_xl[BATCH * SEQ * DM];
__device__ __align__(256) __nv_bfloat16 g_qh[BATCH * SEQ * DM];
__device__ __align__(256) __nv_bfloat16 g_ql[BATCH * SEQ * DM];
__device__ __align__(256) __nv_bfloat16 g_kh[BATCH * SEQ * DM];
__device__ __align__(256) __nv_bfloat16 g_kl[BATCH * SEQ * DM];
__device__ __align__(256) __nv_bfloat16 g_vh[BATCH * SEQ * DM];
__device__ __align__(256) __nv_bfloat16 g_vl[BATCH * SEQ * DM];
__device__ __align__(256) __nv_bfloat16 g_ch[BATCH * SEQ * DM];
__device__ __align__(256) __nv_bfloat16 g_cl[BATCH * SEQ * DM];
__device__ __align__(256) __nv_bfloat16 g_wqh[DM * DM];
__device__ __align__(256) __nv_bfloat16 g_wql[DM * DM];
__device__ __align__(256) __nv_bfloat16 g_wkh[DM * DM];
__device__ __align__(256) __nv_bfloat16 g_wkl[DM * DM];
__device__ __align__(256) __nv_bfloat16 g_wvh[DM * DM];
__device__ __align__(256) __nv_bfloat16 g_wvl[DM * DM];
__device__ __align__(256) __nv_bfloat16 g_woh[DM * DM];
__device__ __align__(256) __nv_bfloat16 g_wol[DM * DM];

// Q pre-scale: 0.125 * log2(e) — S arrives in log2 domain
#define QSCALE 0.18033688011112042f

// ---------------------------------------------------------------------------
// Baseline-PTX helpers (mma.sync / ldmatrix / cp.async — legal on sm_100)
// ---------------------------------------------------------------------------
__device__ __forceinline__ uint32_t smem_u32(const void* p) {
    uint32_t a;
    asm("{ .reg .u64 t; cvta.to.shared.u64 t, %1; cvt.u32.u64 %0, t; }"
        : "=r"(a) : "l"(p));
    return a;
}

__device__ __forceinline__ void ldmx4(uint32_t* r, uint32_t addr) {
    asm volatile("ldmatrix.sync.aligned.m8n8.x4.shared.b16 {%0,%1,%2,%3}, [%4];"
                 : "=r"(r[0]), "=r"(r[1]), "=r"(r[2]), "=r"(r[3]) : "r"(addr));
}

__device__ __forceinline__ void ldmx4t(uint32_t* r, uint32_t addr) {
    asm volatile("ldmatrix.sync.aligned.m8n8.x4.trans.shared.b16 {%0,%1,%2,%3}, [%4];"
                 : "=r"(r[0]), "=r"(r[1]), "=r"(r[2]), "=r"(r[3]) : "r"(addr));
}

__device__ __forceinline__ void mma_bf16(float* c, const uint32_t* a,
                                         uint32_t b0, uint32_t b1) {
    asm volatile(
        "mma.sync.aligned.m16n8k16.row.col.f32.bf16.bf16.f32 "
        "{%0,%1,%2,%3}, {%4,%5,%6,%7}, {%8,%9}, {%0,%1,%2,%3};"
        : "+f"(c[0]), "+f"(c[1]), "+f"(c[2]), "+f"(c[3])
        : "r"(a[0]), "r"(a[1]), "r"(a[2]), "r"(a[3]), "r"(b0), "r"(b1));
}

#define CP_ASYNC16(dst, src) \
    asm volatile("cp.async.cg.shared.global [%0], [%1], 16;" \
                 :: "r"(dst), "l"(src) : "memory")
#define CP_COMMIT()  asm volatile("cp.async.commit_group;" ::: "memory")
#define CP_WAIT(n)   asm volatile("cp.async.wait_group %0;" :: "n"(n) : "memory")

// pack two fp32 into bf16x2 reg (rn; intrinsic, arch-safe)
__device__ __forceinline__ uint32_t packh(float lo, float hi) {
    __nv_bfloat162 t = __floats2bfloat162_rn(lo, hi);
    return *(uint32_t*)&t;
}

// PRMT trunc-split helpers: hi pair = high halves of two fp32 (1 ALU op);
// residual = v - trunc16(v), exact in fp32.
__device__ __forceinline__ uint32_t pack_hi_trunc(float a, float b) {
    return __byte_perm(__float_as_uint(a), __float_as_uint(b), 0x7632);
}
__device__ __forceinline__ float resid16(float v) {
    return v - __uint_as_float(__float_as_uint(v) & 0xffff0000u);
}

// exp2(d) for d <= 0, deg-5 poly on r in [-0.5, 0.5]. FMA-pipe only.
__device__ __forceinline__ float fexp2_raw(float d) {
    float t = fmaxf(d, -115.0f);
    int   e = __float2int_rn(t);
    float r = t - (float)e;
    float p = 1.3333558146e-3f;
    p = fmaf(p, r, 9.6181291076e-3f);
    p = fmaf(p, r, 5.5504108665e-2f);
    p = fmaf(p, r, 2.4022650696e-1f);
    p = fmaf(p, r, 6.9314718056e-1f);
    p = fmaf(p, r, 1.0f);
    return __int_as_float(__float_as_int(p) + (e << 23));
}

// ---------------------------------------------------------------------------
// fp32 -> (hi, lo) bf16 trunc-split, vectorized by 4
// ---------------------------------------------------------------------------
__global__ void split_f32(const float* __restrict__ in,
                          __nv_bfloat16* __restrict__ hi,
                          __nv_bfloat16* __restrict__ lo, int n4)
{
    int i = blockIdx.x * blockDim.x + threadIdx.x;
    if (i >= n4) return;
    float4 v = ((const float4*)in)[i];
    uint32_t* hp = (uint32_t*)hi;
    uint32_t* lp = (uint32_t*)lo;
    hp[2 * i]     = pack_hi_trunc(v.x, v.y);
    hp[2 * i + 1] = pack_hi_trunc(v.z, v.w);
    lp[2 * i]     = packh(resid16(v.x), resid16(v.y));
    lp[2 * i + 1] = packh(resid16(v.z), resid16(v.w));
}

// ---------------------------------------------------------------------------
// GEMM tile machinery shared by gemm_qkv / gemm_out.
// 128x128 CTA tile, BK=32, 8 warps (2x4), warp tile 64x32, m16n8k16.
// ---------------------------------------------------------------------------
#define LDS       40
#define TILE_E    (128 * LDS)
#define TILE_B2   (TILE_E * 2)
#define STAGE_B2  (4 * TILE_B2)
#define GEMM_SMEM (2 * STAGE_B2)

struct GemmCtx {
    uint32_t smb, d0, d1, aoff, boff;
    int tid, lane, wid, wm, wn;
    int r0c, c0c, r1c, c1c;
};

__device__ __forceinline__ void gemm_mainloop(
    const GemmCtx& cx,
    const __nv_bfloat16* const* gsrc, float acc[4][4][4])
{
    const int K = DM;
    const int KSTAGES = K / 32;
    {
        const uint32_t sb = cx.smb;
#pragma unroll
        for (int t = 0; t < 4; t++) {
            const __nv_bfloat16* g = gsrc[t];
            CP_ASYNC16(sb + t * TILE_B2 + cx.d0, g + (size_t)cx.r0c * K + cx.c0c * 8);
            CP_ASYNC16(sb + t * TILE_B2 + cx.d1, g + (size_t)cx.r1c * K + cx.c1c * 8);
        }
        CP_COMMIT();
    }
#pragma unroll 1
    for (int kt = 0; kt < KSTAGES; kt++) {
        if (kt + 1 < KSTAGES) {
            const uint32_t sb = cx.smb + ((kt + 1) & 1) * STAGE_B2;
            const int kk = (kt + 1) * 32;
#pragma unroll
            for (int t = 0; t < 4; t++) {
                const __nv_bfloat16* g = gsrc[t];
                CP_ASYNC16(sb + t * TILE_B2 + cx.d0, g + (size_t)cx.r0c * K + kk + cx.c0c * 8);
                CP_ASYNC16(sb + t * TILE_B2 + cx.d1, g + (size_t)cx.r1c * K + kk + cx.c1c * 8);
            }
            CP_COMMIT();
            CP_WAIT(1);
        } else {
            CP_WAIT(0);
        }
        __syncthreads();

        const uint32_t sb  = cx.smb + (kt & 1) * STAGE_B2;
        const uint32_t sAh = sb;
        const uint32_t sAl = sb + TILE_B2;
        const uint32_t sBh = sb + 2 * TILE_B2;
        const uint32_t sBl = sb + 3 * TILE_B2;

#pragma unroll
        for (int ks = 0; ks < 2; ks++) {
            uint32_t ah[4][4], al[4][4], bh[2][4], bl[2][4];
#pragma unroll
            for (int i = 0; i < 4; i++) {
                uint32_t o = (cx.aoff + (uint32_t)((cx.wm * 64 + i * 16) * LDS + ks * 16)) * 2;
                ldmx4(ah[i], sAh + o);
                ldmx4(al[i], sAl + o);
            }
#pragma unroll
            for (int p = 0; p < 2; p++) {
                uint32_t o = (cx.boff + (uint32_t)((cx.wn * 32 + p * 16) * LDS + ks * 16)) * 2;
                ldmx4(bh[p], sBh + o);
                ldmx4(bl[p], sBl + o);
            }
#pragma unroll
            for (int i = 0; i < 4; i++) {
#pragma unroll
                for (int j = 0; j < 4; j++) {
                    const int p = j >> 1, jj = j & 1;
                    mma_bf16(acc[i][j], ah[i], bh[p][2 * jj], bh[p][2 * jj + 1]);
                    mma_bf16(acc[i][j], ah[i], bl[p][2 * jj], bl[p][2 * jj + 1]);
                    mma_bf16(acc[i][j], al[i], bh[p][2 * jj], bh[p][2 * jj + 1]);
                }
            }
        }
        __syncthreads();
    }
}

__device__ __forceinline__ GemmCtx make_ctx(uint32_t smb) {
    GemmCtx cx;
    cx.smb = smb;
    cx.tid = threadIdx.x;
    cx.lane = cx.tid & 31;
    cx.wid = cx.tid >> 5;
    cx.wm = cx.wid & 1;
    cx.wn = cx.wid >> 1;
    const int ch0 = cx.tid, ch1 = cx.tid + 256;
    cx.r0c = ch0 >> 2; cx.c0c = ch0 & 3;
    cx.r1c = ch1 >> 2; cx.c1c = ch1 & 3;
    cx.d0 = (uint32_t)(cx.r0c * LDS + cx.c0c * 8) * 2;
    cx.d1 = (uint32_t)(cx.r1c * LDS + cx.c1c * 8) * 2;
    const int aq = cx.lane >> 3, ar = cx.lane & 7;
    cx.aoff = (uint32_t)(((aq & 1) * 8 + ar) * LDS + (aq >> 1) * 8);
    cx.boff = (uint32_t)(((aq >> 1) * 8 + ar) * LDS + (aq & 1) * 8);
    return cx;
}

// QKV fused: gridDim.z in {0,1,2} selects weight/output set; split epilogue.
__global__ __launch_bounds__(256, 1)
void gemm_qkv(const __nv_bfloat16* __restrict__ Ah, const __nv_bfloat16* __restrict__ Al,
              const __nv_bfloat16* __restrict__ Bqh, const __nv_bfloat16* __restrict__ Bql,
              const __nv_bfloat16* __restrict__ Bkh, const __nv_bfloat16* __restrict__ Bkl,
              const __nv_bfloat16* __restrict__ Bvh, const __nv_bfloat16* __restrict__ Bvl,
              __nv_bfloat16* __restrict__ Cqh, __nv_bfloat16* __restrict__ Cql,
              __nv_bfloat16* __restrict__ Ckh, __nv_bfloat16* __restrict__ Ckl,
              __nv_bfloat16* __restrict__ Cvh, __nv_bfloat16* __restrict__ Cvl)
{
    extern __shared__ char dsm[];
    GemmCtx cx = make_ctx(smem_u32(dsm));

    const __nv_bfloat16 *Bh, *Bl;
    __nv_bfloat16 *Ch, *Cl;
    float oscale;
    if (blockIdx.z == 0)      { Bh = Bqh; Bl = Bql; Ch = Cqh; Cl = Cql; oscale = QSCALE; }
    else if (blockIdx.z == 1) { Bh = Bkh; Bl = Bkl; Ch = Ckh; Cl = Ckl; oscale = 1.0f; }
    else                      { Bh = Bvh; Bl = Bvl; Ch = Cvh; Cl = Cvl; oscale = 1.0f; }

    const int row0 = blockIdx.y * 128;
    const int col0 = blockIdx.x * 128;
    const __nv_bfloat16* gsrc[4] = {
        Ah + (size_t)row0 * DM, Al + (size_t)row0 * DM,
        Bh + (size_t)col0 * DM, Bl + (size_t)col0 * DM
    };

    float acc[4][4][4];
#pragma unroll
    for (int i = 0; i < 4; i++)
#pragma unroll
        for (int j = 0; j < 4; j++)
#pragma unroll
            for (int r = 0; r < 4; r++) acc[i][j][r] = 0.0f;

    gemm_mainloop(cx, gsrc, acc);

    const int mbase = row0 + cx.wm * 64 + (cx.lane >> 2);
    const int nbase = col0 + cx.wn * 32 + (cx.lane & 3) * 2;
#pragma unroll
    for (int i = 0; i < 4; i++) {
#pragma unroll
        for (int j = 0; j < 4; j++) {
            const int r = mbase + i * 16;
            const int c = nbase + j * 8;
#pragma unroll
            for (int hrow = 0; hrow < 2; hrow++) {
                float v0 = acc[i][j][2 * hrow]     * oscale;
                float v1 = acc[i][j][2 * hrow + 1] * oscale;
                size_t off = (size_t)(r + 8 * hrow) * DM + c;
                *(uint32_t*)&Ch[off] = pack_hi_trunc(v0, v1);
                *(uint32_t*)&Cl[off] = packh(resid16(v0), resid16(v1));
            }
        }
    }
}

// Output projection: fp32 epilogue.
__global__ __launch_bounds__(256, 1)
void gemm_out(const __nv_bfloat16* __restrict__ Ah, const __nv_bfloat16* __restrict__ Al,
              const __nv_bfloat16* __restrict__ Bh, const __nv_bfloat16* __restrict__ Bl,
              float* __restrict__ C)
{
    extern __shared__ char dsm[];
    GemmCtx cx = make_ctx(smem_u32(dsm));

    const int row0 = blockIdx.y * 128;
    const int col0 = blockIdx.x * 128;
    const __nv_bfloat16* gsrc[4] = {
        Ah + (size_t)row0 * DM, Al + (size_t)row0 * DM,
        Bh + (size_t)col0 * DM, Bl + (size_t)col0 * DM
    };

    float acc[4][4][4];
#pragma unroll
    for (int i = 0; i < 4; i++)
#pragma unroll
        for (int j = 0; j < 4; j++)
#pragma unroll
            for (int r = 0; r < 4; r++) acc[i][j][r] = 0.0f;

    gemm_mainloop(cx, gsrc, acc);

    const int mbase = row0 + cx.wm * 64 + (cx.lane >> 2);
    const int nbase = col0 + cx.wn * 32 + (cx.lane & 3) * 2;
#pragma unroll
    for (int i = 0; i < 4; i++) {
#pragma unroll
        for (int j = 0; j < 4; j++) {
            const int r = mbase + i * 16;
            const int c = nbase + j * 8;
            *(float2*)&C[(size_t)r * DM + c]       = make_float2(acc[i][j][0], acc[i][j][1]);
            *(float2*)&C[(size_t)(r + 8) * DM + c] = make_float2(acc[i][j][2], acc[i][j][3]);
        }
    }
}

// ---------------------------------------------------------------------------
// Causal flash attention on mma.sync, split-bf16, FMA-pipe exp2.
// SMALL CTA: 128 threads (4 warps x 16 rows = Br 64), Bc=64, smem 92 KB.
// Two independent CTAs co-reside per SM -> each SMSP interleaves warps from
// two uncorrelated barrier domains, hiding softmax/ldmatrix latency under
// the other CTA's mma stream. No launch-bounds register cap needed.
// ---------------------------------------------------------------------------
#define FLDS      72                  // padded row stride (bf16), 144 B
#define QBUF_B    (64 * FLDS * 2)     // 9216
#define KVBUF_B   (64 * FLDS * 2)     // 9216
#define KVSTAGE_B (4 * KVBUF_B)       // 36864 (kh,kl,vh,vl)
#define FLASH_SMEM (2 * QBUF_B + 2 * KVSTAGE_B)   // 92160

__global__ __launch_bounds__(128)
void flash_mma(const __nv_bfloat16* __restrict__ qh_g, const __nv_bfloat16* __restrict__ ql_g,
               const __nv_bfloat16* __restrict__ kh_g, const __nv_bfloat16* __restrict__ kl_g,
               const __nv_bfloat16* __restrict__ vh_g, const __nv_bfloat16* __restrict__ vl_g,
               __nv_bfloat16* __restrict__ ch_g, __nv_bfloat16* __restrict__ cl_g)
{
    extern __shared__ char dsm[];
    const uint32_t smb = smem_u32(dsm);
    const uint32_t sq  = smb;
    const uint32_t skv = smb + 2 * QBUF_B;

    const int tid  = threadIdx.x;
    const int lane = tid & 31;
    const int wid  = tid >> 5;            // 0..3
    const int qb   = (int)(gridDim.x - 1 - blockIdx.x);   // longest-first, 0..31
    const int b    = blockIdx.y >> 4;
    const int h    = blockIdx.y & 15;
    const int q0   = qb * 64;
    const size_t gbase = (size_t)b * SEQ * DM + h * HD;

    const int ar = lane & 7, asub = lane >> 3;
    const uint32_t aoff = (uint32_t)(((asub & 1) * 8 + ar) * FLDS + (asub >> 1) * 8);
    const uint32_t boff = (uint32_t)(((asub >> 1) * 8 + ar) * FLDS + (asub & 1) * 8);

    const __nv_bfloat16* kvsrc[4] = {kh_g, kl_g, vh_g, vl_g};

    // ---- kv tile 0 prefetch + Q load (128 threads) ----
    {
#pragma unroll
        for (int kk = 0; kk < 16; kk++) {
            int id = tid + kk * 128;          // 0..2047
            int buf = id >> 9, row = (id >> 3) & 63, cc = id & 7;
            CP_ASYNC16(skv + buf * KVBUF_B + row * 144 + cc * 16,
                       kvsrc[buf] + gbase + (size_t)row * DM + cc * 8);
        }
        CP_COMMIT();
#pragma unroll
        for (int kk = 0; kk < 8; kk++) {
            int id = tid + kk * 128;          // 0..1023
            int buf = id >> 9, row = (id >> 3) & 63, cc = id & 7;
            const __nv_bfloat16* src = (buf ? ql_g : qh_g) + gbase +
                                       (size_t)(q0 + row) * DM + cc * 8;
            CP_ASYNC16(sq + buf * QBUF_B + row * 144 + cc * 16, src);
        }
        CP_COMMIT();
        CP_WAIT(0);
        __syncthreads();
    }

    uint32_t qhf[4][4], qlf[4][4];
#pragma unroll
    for (int kc = 0; kc < 4; kc++) {
        uint32_t o = (aoff + (uint32_t)(wid * 16 * FLDS + kc * 16)) * 2;
        ldmx4(qhf[kc], sq + o);
        ldmx4(qlf[kc], sq + QBUF_B + o);
    }

    float acc[8][4];
#pragma unroll
    for (int f = 0; f < 8; f++)
#pragma unroll
        for (int r = 0; r < 4; r++) acc[f][r] = 0.0f;
    float m0 = -1e30f, m1 = -1e30f, l0 = 0.0f, l1 = 0.0f;

    const int T  = qb + 1;
    const int rr = lane >> 2, qx = lane & 3;
    const int rowg0 = q0 + wid * 16 + rr;

#pragma unroll 1
    for (int t = 0; t < T; t++) {
        if (t + 1 < T) {
            const uint32_t sb = skv + ((t + 1) & 1) * KVSTAGE_B;
            const int s1 = (t + 1) * 64;
#pragma unroll
            for (int kk = 0; kk < 16; kk++) {
                int id = tid + kk * 128;
                int buf = id >> 9, row = (id >> 3) & 63, cc = id & 7;
                CP_ASYNC16(sb + buf * KVBUF_B + row * 144 + cc * 16,
                           kvsrc[buf] + gbase + (size_t)(s1 + row) * DM + cc * 8);
            }
            CP_COMMIT();
            CP_WAIT(1);
        } else {
            CP_WAIT(0);
        }
        __syncthreads();

        const uint32_t st = skv + (t & 1) * KVSTAGE_B;

        // ---- S = Q K^T (split, 3 passes) ----
        float s[8][4];
#pragma unroll
        for (int f = 0; f < 8; f++)
#pragma unroll
            for (int r = 0; r < 4; r++) s[f][r] = 0.0f;

#pragma unroll
        for (int kc = 0; kc < 4; kc++) {
#pragma unroll
            for (int p = 0; p < 4; p++) {
                uint32_t o = (boff + (uint32_t)(p * 16 * FLDS + kc * 16)) * 2;
                uint32_t kbh[4], kbl[4];
                ldmx4(kbh, st + o);
                ldmx4(kbl, st + KVBUF_B + o);
                mma_bf16(s[2 * p],     qhf[kc], kbh[0], kbh[1]);
                mma_bf16(s[2 * p + 1], qhf[kc], kbh[2], kbh[3]);
                mma_bf16(s[2 * p],     qhf[kc], kbl[0], kbl[1]);
                mma_bf16(s[2 * p + 1], qhf[kc], kbl[2], kbl[3]);
                mma_bf16(s[2 * p],     qlf[kc], kbh[0], kbh[1]);
                mma_bf16(s[2 * p + 1], qlf[kc], kbh[2], kbh[3]);
            }
        }

        // ---- causal mask (diagonal tile only: t == qb) ----
        const int s0 = t * 64;
        if (s0 + 63 > q0) {
#pragma unroll
            for (int f = 0; f < 8; f++) {
                int c0 = s0 + f * 8 + 2 * qx;
                if (c0 > rowg0)         s[f][0] = -1e30f;
                if (c0 + 1 > rowg0)     s[f][1] = -1e30f;
                if (c0 > rowg0 + 8)     s[f][2] = -1e30f;
                if (c0 + 1 > rowg0 + 8) s[f][3] = -1e30f;
            }
        }

        // ---- online softmax in log2 domain (quad shfl reductions) ----
        {
            float mx = -1e30f;
#pragma unroll
            for (int f = 0; f < 8; f++) mx = fmaxf(mx, fmaxf(s[f][0], s[f][1]));
            mx = fmaxf(mx, __shfl_xor_sync(0xffffffffu, mx, 1));
            mx = fmaxf(mx, __shfl_xor_sync(0xffffffffu, mx, 2));
            float mn = fmaxf(m0, mx);
            float al = fexp2_raw(m0 - mn);
            m0 = mn;
            float sum = 0.0f;
#pragma unroll
            for (int f = 0; f < 8; f++) {
                s[f][0] = fexp2_raw(s[f][0] - mn);
                s[f][1] = fexp2_raw(s[f][1] - mn);
                sum += s[f][0] + s[f][1];
            }
            sum += __shfl_xor_sync(0xffffffffu, sum, 1);
            sum += __shfl_xor_sync(0xffffffffu, sum, 2);
            l0 = l0 * al + sum;
#pragma unroll
            for (int f = 0; f < 8; f++) { acc[f][0] *= al; acc[f][1] *= al; }
        }
        {
            float mx = -1e30f;
#pragma unroll
            for (int f = 0; f < 8; f++) mx = fmaxf(mx, fmaxf(s[f][2], s[f][3]));
            mx = fmaxf(mx, __shfl_xor_sync(0xffffffffu, mx, 1));
            mx = fmaxf(mx, __shfl_xor_sync(0xffffffffu, mx, 2));
            float mn = fmaxf(m1, mx);
            float al = fexp2_raw(m1 - mn);
            m1 = mn;
            float sum = 0.0f;
#pragma unroll
            for (int f = 0; f < 8; f++) {
                s[f][2] = fexp2_raw(s[f][2] - mn);
                s[f][3] = fexp2_raw(s[f][3] - mn);
                sum += s[f][2] + s[f][3];
            }
            sum += __shfl_xor_sync(0xffffffffu, sum, 1);
            sum += __shfl_xor_sync(0xffffffffu, sum, 2);
            l1 = l1 * al + sum;
#pragma unroll
            for (int f = 0; f < 8; f++) { acc[f][2] *= al; acc[f][3] *= al; }
        }

        // ---- O += P V (split, 3 passes; P stays in registers) ----
#pragma unroll
        for (int jc = 0; jc < 4; jc++) {
            const float* sA = s[2 * jc];
            const float* sB = s[2 * jc + 1];
            uint32_t pha[4], pla[4];
            pha[0] = pack_hi_trunc(sA[0], sA[1]);
            pha[1] = pack_hi_trunc(sA[2], sA[3]);
            pha[2] = pack_hi_trunc(sB[0], sB[1]);
            pha[3] = pack_hi_trunc(sB[2], sB[3]);
            pla[0] = packh(resid16(sA[0]), resid16(sA[1]));
            pla[1] = packh(resid16(sA[2]), resid16(sA[3]));
            pla[2] = packh(resid16(sB[0]), resid16(sB[1]));
            pla[3] = packh(resid16(sB[2]), resid16(sB[3]));
#pragma unroll
            for (int pe = 0; pe < 4; pe++) {
                uint32_t o = (aoff + (uint32_t)(jc * 16 * FLDS + pe * 16)) * 2;
                uint32_t vbh[4], vbl[4];
                ldmx4t(vbh, st + 2 * KVBUF_B + o);
                ldmx4t(vbl, st + 3 * KVBUF_B + o);
                mma_bf16(acc[2 * pe],     pha, vbh[0], vbh[1]);
                mma_bf16(acc[2 * pe + 1], pha, vbh[2], vbh[3]);
                mma_bf16(acc[2 * pe],     pha, vbl[0], vbl[1]);
                mma_bf16(acc[2 * pe + 1], pha, vbl[2], vbl[3]);
                mma_bf16(acc[2 * pe],     pla, vbh[0], vbh[1]);
                mma_bf16(acc[2 * pe + 1], pla, vbh[2], vbh[3]);
            }
        }
        __syncthreads();
    }

    // ---- epilogue: normalize, trunc-split to bf16 hi/lo, store ----
    const float inv0 = 1.0f / l0;
    const float inv1 = 1.0f / l1;
#pragma unroll
    for (int f = 0; f < 8; f++) {
        const int coloff = f * 8 + 2 * qx;
#pragma unroll
        for (int hrow = 0; hrow < 2; hrow++) {
            float inv = hrow ? inv1 : inv0;
            float v0 = acc[f][2 * hrow]     * inv;
            float v1 = acc[f][2 * hrow + 1] * inv;
            size_t off = gbase + (size_t)(rowg0 + 8 * hrow) * DM + coloff;
            *(uint32_t*)&ch_g[off] = pack_hi_trunc(v0, v1);
            *(uint32_t*)&cl_g[off] = packh(resid16(v0), resid16(v1));
        }
    }
}

// ---------------------------------------------------------------------------
extern "C" void kernel_launch(void* const* d_in, const int* in_sizes, int n_in,
                              void* d_out, int out_size)
{
    const float* x  = (const float*)d_in[0];
    const float* Wq = (const float*)d_in[1];
    const float* Wk = (const float*)d_in[2];
    const float* Wv = (const float*)d_in[3];
    const float* Wo = (const float*)d_in[4];
    float* out = (float*)d_out;

    __nv_bfloat16 *xh, *xl, *qh, *ql, *kh, *kl, *vh, *vl, *ch, *cl;
    __nv_bfloat16 *wqh, *wql, *wkh, *wkl, *wvh, *wvl, *woh, *wol;
    cudaGetSymbolAddress((void**)&xh, g_xh);
    cudaGetSymbolAddress((void**)&xl, g_xl);
    cudaGetSymbolAddress((void**)&qh, g_qh);
    cudaGetSymbolAddress((void**)&ql, g_ql);
    cudaGetSymbolAddress((void**)&kh, g_kh);
    cudaGetSymbolAddress((void**)&kl, g_kl);
    cudaGetSymbolAddress((void**)&vh, g_vh);
    cudaGetSymbolAddress((void**)&vl, g_vl);
    cudaGetSymbolAddress((void**)&ch, g_ch);
    cudaGetSymbolAddress((void**)&cl, g_cl);
    cudaGetSymbolAddress((void**)&wqh, g_wqh);
    cudaGetSymbolAddress((void**)&wql, g_wql);
    cudaGetSymbolAddress((void**)&wkh, g_wkh);
    cudaGetSymbolAddress((void**)&wkl, g_wkl);
    cudaGetSymbolAddress((void**)&wvh, g_wvh);
    cudaGetSymbolAddress((void**)&wvl, g_wvl);
    cudaGetSymbolAddress((void**)&woh, g_woh);
    cudaGetSymbolAddress((void**)&wol, g_wol);

    cudaFuncSetAttribute(gemm_qkv,
                         cudaFuncAttributeMaxDynamicSharedMemorySize, GEMM_SMEM);
    cudaFuncSetAttribute(gemm_out,
                         cudaFuncAttributeMaxDynamicSharedMemorySize, GEMM_SMEM);
    cudaFuncSetAttribute(flash_mma,
                         cudaFuncAttributeMaxDynamicSharedMemorySize, FLASH_SMEM);

    const int M  = BATCH * SEQ;           // 8192
    const int n4x = M * DM / 4;
    const int n4w = DM * DM / 4;

    // fp32 -> bf16 hi/lo splits (input + weights only)
    split_f32<<<n4x / 256, 256>>>(x, xh, xl, n4x);
    split_f32<<<n4w / 256, 256>>>(Wq, wqh, wql, n4w);
    split_f32<<<n4w / 256, 256>>>(Wk, wkh, wkl, n4w);
    split_f32<<<n4w / 256, 256>>>(Wv, wvh, wvl, n4w);
    split_f32<<<n4w / 256, 256>>>(Wo, woh, wol, n4w);

    // Fused QKV projections (one launch, z selects weight set; Q pre-scaled)
    dim3 gqkv(DM / 128, M / 128, 3);      // (8, 64, 3) = 1536 CTAs
    gemm_qkv<<<gqkv, 256, GEMM_SMEM>>>(xh, xl,
                                       wqh, wql, wkh, wkl, wvh, wvl,
                                       qh, ql, kh, kl, vh, vl);

    // causal attention: 128-thread CTAs, 2 per SM co-resident
    flash_mma<<<dim3(SEQ / 64, BATCH * NH), 128, FLASH_SMEM>>>(
        qh, ql, kh, kl, vh, vl, ch, cl);

    // output projection (fp32 out)
    gemm_out<<<dim3(DM / 128, M / 128), 256, GEMM_SMEM>>>(ch, cl, woh, wol, out);
}

// round 12
// speedup vs baseline: 2.8520x; 1.1123x over previous
#include <cuda_runtime.h>
#include <cuda_bf16.h>
#include <cstdint>

#define SEQ   2048
#define BATCH 4
#define NH    16
#define DM    1024
#define HD    64

// ---------------------------------------------------------------------------
// Scratch (__device__ globals; no allocation allowed anywhere)
// ---------------------------------------------------------------------------
__device__ __align__(256) __nv_bfloat16 g_xh[BATCH * SEQ * DM];
__device__ __align__(256) __nv_bfloat16 g_xl[BATCH * SEQ * DM];
__device__ __align__(256) __nv_bfloat16 g_qh[BATCH * SEQ * DM];
__device__ __align__(256) __nv_bfloat16 g_ql[BATCH * SEQ * DM];
__device__ __align__(256) __nv_bfloat16 g_kh[BATCH * SEQ * DM];
__device__ __align__(256) __nv_bfloat16 g_kl[BATCH * SEQ * DM];
__device__ __align__(256) __nv_bfloat16 g_vh[BATCH * SEQ * DM];
__device__ __align__(256) __nv_bfloat16 g_vl[BATCH * SEQ * DM];
__device__ __align__(256) __nv_bfloat16 g_ch[BATCH * SEQ * DM];
__device__ __align__(256) __nv_bfloat16 g_cl[BATCH * SEQ * DM];
__device__ __align__(256) __nv_bfloat16 g_wqh[DM * DM];
__device__ __align__(256) __nv_bfloat16 g_wql[DM * DM];
__device__ __align__(256) __nv_bfloat16 g_wkh[DM * DM];
__device__ __align__(256) __nv_bfloat16 g_wkl[DM * DM];
__device__ __align__(256) __nv_bfloat16 g_wvh[DM * DM];
__device__ __align__(256) __nv_bfloat16 g_wvl[DM * DM];
__device__ __align__(256) __nv_bfloat16 g_woh[DM * DM];
__device__ __align__(256) __nv_bfloat16 g_wol[DM * DM];

// Q pre-scale: 0.125 * log2(e) — S arrives in log2 domain
#define QSCALE 0.18033688011112042f

// ---------------------------------------------------------------------------
// Baseline-PTX helpers (mma.sync / ldmatrix / cp.async — legal on sm_100)
// ---------------------------------------------------------------------------
__device__ __forceinline__ uint32_t smem_u32(const void* p) {
    uint32_t a;
    asm("{ .reg .u64 t; cvta.to.shared.u64 t, %1; cvt.u32.u64 %0, t; }"
        : "=r"(a) : "l"(p));
    return a;
}

__device__ __forceinline__ void ldmx4(uint32_t* r, uint32_t addr) {
    asm volatile("ldmatrix.sync.aligned.m8n8.x4.shared.b16 {%0,%1,%2,%3}, [%4];"
                 : "=r"(r[0]), "=r"(r[1]), "=r"(r[2]), "=r"(r[3]) : "r"(addr));
}

__device__ __forceinline__ void ldmx4t(uint32_t* r, uint32_t addr) {
    asm volatile("ldmatrix.sync.aligned.m8n8.x4.trans.shared.b16 {%0,%1,%2,%3}, [%4];"
                 : "=r"(r[0]), "=r"(r[1]), "=r"(r[2]), "=r"(r[3]) : "r"(addr));
}

__device__ __forceinline__ void mma_bf16(float* c, const uint32_t* a,
                                         uint32_t b0, uint32_t b1) {
    asm volatile(
        "mma.sync.aligned.m16n8k16.row.col.f32.bf16.bf16.f32 "
        "{%0,%1,%2,%3}, {%4,%5,%6,%7}, {%8,%9}, {%0,%1,%2,%3};"
        : "+f"(c[0]), "+f"(c[1]), "+f"(c[2]), "+f"(c[3])
        : "r"(a[0]), "r"(a[1]), "r"(a[2]), "r"(a[3]), "r"(b0), "r"(b1));
}

#define CP_ASYNC16(dst, src) \
    asm volatile("cp.async.cg.shared.global [%0], [%1], 16;" \
                 :: "r"(dst), "l"(src) : "memory")
#define CP_COMMIT()  asm volatile("cp.async.commit_group;" ::: "memory")
#define CP_WAIT(n)   asm volatile("cp.async.wait_group %0;" :: "n"(n) : "memory")

// pack two fp32 into bf16x2 reg (rn; intrinsic, arch-safe)
__device__ __forceinline__ uint32_t packh(float lo, float hi) {
    __nv_bfloat162 t = __floats2bfloat162_rn(lo, hi);
    return *(uint32_t*)&t;
}

// PRMT trunc-split helpers
__device__ __forceinline__ uint32_t pack_hi_trunc(float a, float b) {
    return __byte_perm(__float_as_uint(a), __float_as_uint(b), 0x7632);
}
__device__ __forceinline__ float resid16(float v) {
    return v - __uint_as_float(__float_as_uint(v) & 0xffff0000u);
}

// exp2(d) for d <= 0, deg-5 poly on r in [-0.5, 0.5]. FMA-pipe only.
__device__ __forceinline__ float fexp2_raw(float d) {
    float t = fmaxf(d, -115.0f);
    int   e = __float2int_rn(t);
    float r = t - (float)e;
    float p = 1.3333558146e-3f;
    p = fmaf(p, r, 9.6181291076e-3f);
    p = fmaf(p, r, 5.5504108665e-2f);
    p = fmaf(p, r, 2.4022650696e-1f);
    p = fmaf(p, r, 6.9314718056e-1f);
    p = fmaf(p, r, 1.0f);
    return __int_as_float(__float_as_int(p) + (e << 23));
}

// ---------------------------------------------------------------------------
// fp32 -> (hi, lo) bf16 trunc-split, vectorized by 4
// ---------------------------------------------------------------------------
__global__ void split_f32(const float* __restrict__ in,
                          __nv_bfloat16* __restrict__ hi,
                          __nv_bfloat16* __restrict__ lo, int n4)
{
    int i = blockIdx.x * blockDim.x + threadIdx.x;
    if (i >= n4) return;
    float4 v = ((const float4*)in)[i];
    uint32_t* hp = (uint32_t*)hi;
    uint32_t* lp = (uint32_t*)lo;
    hp[2 * i]     = pack_hi_trunc(v.x, v.y);
    hp[2 * i + 1] = pack_hi_trunc(v.z, v.w);
    lp[2 * i]     = packh(resid16(v.x), resid16(v.y));
    lp[2 * i + 1] = packh(resid16(v.z), resid16(v.w));
}

// 4 weight splits fused in one launch (blockIdx.y selects tensor)
__global__ void split_w4(const float* __restrict__ W0, const float* __restrict__ W1,
                         const float* __restrict__ W2, const float* __restrict__ W3,
                         __nv_bfloat16* __restrict__ H0, __nv_bfloat16* __restrict__ L0,
                         __nv_bfloat16* __restrict__ H1, __nv_bfloat16* __restrict__ L1,
                         __nv_bfloat16* __restrict__ H2, __nv_bfloat16* __restrict__ L2,
                         __nv_bfloat16* __restrict__ H3, __nv_bfloat16* __restrict__ L3,
                         int n4)
{
    int i = blockIdx.x * blockDim.x + threadIdx.x;
    if (i >= n4) return;
    const float* in; __nv_bfloat16 *hi, *lo;
    switch (blockIdx.y) {
        case 0:  in = W0; hi = H0; lo = L0; break;
        case 1:  in = W1; hi = H1; lo = L1; break;
        case 2:  in = W2; hi = H2; lo = L2; break;
        default: in = W3; hi = H3; lo = L3; break;
    }
    float4 v = ((const float4*)in)[i];
    uint32_t* hp = (uint32_t*)hi;
    uint32_t* lp = (uint32_t*)lo;
    hp[2 * i]     = pack_hi_trunc(v.x, v.y);
    hp[2 * i + 1] = pack_hi_trunc(v.z, v.w);
    lp[2 * i]     = packh(resid16(v.x), resid16(v.y));
    lp[2 * i + 1] = packh(resid16(v.z), resid16(v.w));
}

// ---------------------------------------------------------------------------
// Small-CTA GEMM: 128 threads, CTA tile 64x128, BK=32, 4 warps (1x4),
// warp tile 64x32, m16n8k16 split-bf16 3-pass. smem 61,440 B -> 3 CTAs/SM.
// ---------------------------------------------------------------------------
#define LDS       40
#define A_T_B     (64 * LDS * 2)              // 5120  (64-row tile)
#define B_T_B     (128 * LDS * 2)             // 10240 (128-row tile)
#define GSTAGE_B  (2 * A_T_B + 2 * B_T_B)     // 30720
#define GEMM_SMEM (2 * GSTAGE_B)              // 61440

struct GemmCtx {
    uint32_t smb, aoff, boff;
    int tid, lane, wid;
};

__device__ __forceinline__ GemmCtx make_ctx(uint32_t smb) {
    GemmCtx cx;
    cx.smb = smb;
    cx.tid = threadIdx.x;
    cx.lane = cx.tid & 31;
    cx.wid = cx.tid >> 5;                     // 0..3 -> 32-col strip
    const int aq = cx.lane >> 3, ar = cx.lane & 7;
    cx.aoff = (uint32_t)(((aq & 1) * 8 + ar) * LDS + (aq >> 1) * 8);
    cx.boff = (uint32_t)(((aq >> 1) * 8 + ar) * LDS + (aq & 1) * 8);
    return cx;
}

// loader for one stage at smem base sb, k-offset kk
__device__ __forceinline__ void gemm_load_stage(
    const GemmCtx& cx, uint32_t sb, int kk,
    const __nv_bfloat16* Ah, const __nv_bfloat16* Al,
    const __nv_bfloat16* Bh, const __nv_bfloat16* Bl)
{
    const int K = DM;
#pragma unroll
    for (int q = 0; q < 2; q++) {             // A: 256 chunks/buf
        int id = cx.tid + q * 128;
        int r = id >> 2, c = id & 3;
        uint32_t d = (uint32_t)(r * LDS + c * 8) * 2;
        CP_ASYNC16(sb + d,         Ah + (size_t)r * K + kk + c * 8);
        CP_ASYNC16(sb + A_T_B + d, Al + (size_t)r * K + kk + c * 8);
    }
#pragma unroll
    for (int q = 0; q < 4; q++) {             // B: 512 chunks/buf
        int id = cx.tid + q * 128;
        int r = id >> 2, c = id & 3;
        uint32_t d = (uint32_t)(r * LDS + c * 8) * 2;
        CP_ASYNC16(sb + 2 * A_T_B + d,         Bh + (size_t)r * K + kk + c * 8);
        CP_ASYNC16(sb + 2 * A_T_B + B_T_B + d, Bl + (size_t)r * K + kk + c * 8);
    }
}

__device__ __forceinline__ void gemm_mainloop(
    const GemmCtx& cx,
    const __nv_bfloat16* Ah, const __nv_bfloat16* Al,
    const __nv_bfloat16* Bh, const __nv_bfloat16* Bl,
    float acc[4][4][4])
{
    const int KSTAGES = DM / 32;
    gemm_load_stage(cx, cx.smb, 0, Ah, Al, Bh, Bl);
    CP_COMMIT();

#pragma unroll 1
    for (int kt = 0; kt < KSTAGES; kt++) {
        if (kt + 1 < KSTAGES) {
            gemm_load_stage(cx, cx.smb + ((kt + 1) & 1) * GSTAGE_B, (kt + 1) * 32,
                            Ah, Al, Bh, Bl);
            CP_COMMIT();
            CP_WAIT(1);
        } else {
            CP_WAIT(0);
        }
        __syncthreads();

        const uint32_t sb  = cx.smb + (kt & 1) * GSTAGE_B;
        const uint32_t sAh = sb;
        const uint32_t sAl = sb + A_T_B;
        const uint32_t sBh = sb + 2 * A_T_B;
        const uint32_t sBl = sb + 2 * A_T_B + B_T_B;

#pragma unroll
        for (int ks = 0; ks < 2; ks++) {
            uint32_t ah[4][4], al[4][4], bh[2][4], bl[2][4];
#pragma unroll
            for (int i = 0; i < 4; i++) {
                uint32_t o = (cx.aoff + (uint32_t)((i * 16) * LDS + ks * 16)) * 2;
                ldmx4(ah[i], sAh + o);
                ldmx4(al[i], sAl + o);
            }
#pragma unroll
            for (int p = 0; p < 2; p++) {
                uint32_t o = (cx.boff + (uint32_t)((cx.wid * 32 + p * 16) * LDS + ks * 16)) * 2;
                ldmx4(bh[p], sBh + o);
                ldmx4(bl[p], sBl + o);
            }
#pragma unroll
            for (int i = 0; i < 4; i++) {
#pragma unroll
                for (int j = 0; j < 4; j++) {
                    const int p = j >> 1, jj = j & 1;
                    mma_bf16(acc[i][j], ah[i], bh[p][2 * jj], bh[p][2 * jj + 1]);
                    mma_bf16(acc[i][j], ah[i], bl[p][2 * jj], bl[p][2 * jj + 1]);
                    mma_bf16(acc[i][j], al[i], bh[p][2 * jj], bh[p][2 * jj + 1]);
                }
            }
        }
        __syncthreads();
    }
}

// QKV fused: gridDim.z selects weight/output set; split epilogue.
__global__ __launch_bounds__(128)
void gemm_qkv(const __nv_bfloat16* __restrict__ Ah, const __nv_bfloat16* __restrict__ Al,
              const __nv_bfloat16* __restrict__ Bqh, const __nv_bfloat16* __restrict__ Bql,
              const __nv_bfloat16* __restrict__ Bkh, const __nv_bfloat16* __restrict__ Bkl,
              const __nv_bfloat16* __restrict__ Bvh, const __nv_bfloat16* __restrict__ Bvl,
              __nv_bfloat16* __restrict__ Cqh, __nv_bfloat16* __restrict__ Cql,
              __nv_bfloat16* __restrict__ Ckh, __nv_bfloat16* __restrict__ Ckl,
              __nv_bfloat16* __restrict__ Cvh, __nv_bfloat16* __restrict__ Cvl)
{
    extern __shared__ char dsm[];
    GemmCtx cx = make_ctx(smem_u32(dsm));

    const __nv_bfloat16 *Bh, *Bl;
    __nv_bfloat16 *Ch, *Cl;
    float oscale;
    if (blockIdx.z == 0)      { Bh = Bqh; Bl = Bql; Ch = Cqh; Cl = Cql; oscale = QSCALE; }
    else if (blockIdx.z == 1) { Bh = Bkh; Bl = Bkl; Ch = Ckh; Cl = Ckl; oscale = 1.0f; }
    else                      { Bh = Bvh; Bl = Bvl; Ch = Cvh; Cl = Cvl; oscale = 1.0f; }

    const int row0 = blockIdx.y * 64;
    const int col0 = blockIdx.x * 128;

    float acc[4][4][4];
#pragma unroll
    for (int i = 0; i < 4; i++)
#pragma unroll
        for (int j = 0; j < 4; j++)
#pragma unroll
            for (int r = 0; r < 4; r++) acc[i][j][r] = 0.0f;

    gemm_mainloop(cx, Ah + (size_t)row0 * DM, Al + (size_t)row0 * DM,
                  Bh + (size_t)col0 * DM, Bl + (size_t)col0 * DM, acc);

    const int mbase = row0 + (cx.lane >> 2);
    const int nbase = col0 + cx.wid * 32 + (cx.lane & 3) * 2;
#pragma unroll
    for (int i = 0; i < 4; i++) {
#pragma unroll
        for (int j = 0; j < 4; j++) {
            const int r = mbase + i * 16;
            const int c = nbase + j * 8;
#pragma unroll
            for (int hrow = 0; hrow < 2; hrow++) {
                float v0 = acc[i][j][2 * hrow]     * oscale;
                float v1 = acc[i][j][2 * hrow + 1] * oscale;
                size_t off = (size_t)(r + 8 * hrow) * DM + c;
                *(uint32_t*)&Ch[off] = pack_hi_trunc(v0, v1);
                *(uint32_t*)&Cl[off] = packh(resid16(v0), resid16(v1));
            }
        }
    }
}

// Output projection: fp32 epilogue.
__global__ __launch_bounds__(128)
void gemm_out(const __nv_bfloat16* __restrict__ Ah, const __nv_bfloat16* __restrict__ Al,
              const __nv_bfloat16* __restrict__ Bh, const __nv_bfloat16* __restrict__ Bl,
              float* __restrict__ C)
{
    extern __shared__ char dsm[];
    GemmCtx cx = make_ctx(smem_u32(dsm));

    const int row0 = blockIdx.y * 64;
    const int col0 = blockIdx.x * 128;

    float acc[4][4][4];
#pragma unroll
    for (int i = 0; i < 4; i++)
#pragma unroll
        for (int j = 0; j < 4; j++)
#pragma unroll
            for (int r = 0; r < 4; r++) acc[i][j][r] = 0.0f;

    gemm_mainloop(cx, Ah + (size_t)row0 * DM, Al + (size_t)row0 * DM,
                  Bh + (size_t)col0 * DM, Bl + (size_t)col0 * DM, acc);

    const int mbase = row0 + (cx.lane >> 2);
    const int nbase = col0 + cx.wid * 32 + (cx.lane & 3) * 2;
#pragma unroll
    for (int i = 0; i < 4; i++) {
#pragma unroll
        for (int j = 0; j < 4; j++) {
            const int r = mbase + i * 16;
            const int c = nbase + j * 8;
            *(float2*)&C[(size_t)r * DM + c]       = make_float2(acc[i][j][0], acc[i][j][1]);
            *(float2*)&C[(size_t)(r + 8) * DM + c] = make_float2(acc[i][j][2], acc[i][j][3]);
        }
    }
}

// ---------------------------------------------------------------------------
// Causal flash attention (unchanged from round 11: 128-thread CTA, Br=64,
// Bc=64, 92 KB smem, 2 CTAs/SM co-resident)
// ---------------------------------------------------------------------------
#define FLDS      72
#define QBUF_B    (64 * FLDS * 2)     // 9216
#define KVBUF_B   (64 * FLDS * 2)     // 9216
#define KVSTAGE_B (4 * KVBUF_B)       // 36864
#define FLASH_SMEM (2 * QBUF_B + 2 * KVSTAGE_B)   // 92160

__global__ __launch_bounds__(128)
void flash_mma(const __nv_bfloat16* __restrict__ qh_g, const __nv_bfloat16* __restrict__ ql_g,
               const __nv_bfloat16* __restrict__ kh_g, const __nv_bfloat16* __restrict__ kl_g,
               const __nv_bfloat16* __restrict__ vh_g, const __nv_bfloat16* __restrict__ vl_g,
               __nv_bfloat16* __restrict__ ch_g, __nv_bfloat16* __restrict__ cl_g)
{
    extern __shared__ char dsm[];
    const uint32_t smb = smem_u32(dsm);
    const uint32_t sq  = smb;
    const uint32_t skv = smb + 2 * QBUF_B;

    const int tid  = threadIdx.x;
    const int lane = tid & 31;
    const int wid  = tid >> 5;
    const int qb   = (int)(gridDim.x - 1 - blockIdx.x);
    const int b    = blockIdx.y >> 4;
    const int h    = blockIdx.y & 15;
    const int q0   = qb * 64;
    const size_t gbase = (size_t)b * SEQ * DM + h * HD;

    const int ar = lane & 7, asub = lane >> 3;
    const uint32_t aoff = (uint32_t)(((asub & 1) * 8 + ar) * FLDS + (asub >> 1) * 8);
    const uint32_t boff = (uint32_t)(((asub >> 1) * 8 + ar) * FLDS + (asub & 1) * 8);

    const __nv_bfloat16* kvsrc[4] = {kh_g, kl_g, vh_g, vl_g};

    {
#pragma unroll
        for (int kk = 0; kk < 16; kk++) {
            int id = tid + kk * 128;
            int buf = id >> 9, row = (id >> 3) & 63, cc = id & 7;
            CP_ASYNC16(skv + buf * KVBUF_B + row * 144 + cc * 16,
                       kvsrc[buf] + gbase + (size_t)row * DM + cc * 8);
        }
        CP_COMMIT();
#pragma unroll
        for (int kk = 0; kk < 8; kk++) {
            int id = tid + kk * 128;
            int buf = id >> 9, row = (id >> 3) & 63, cc = id & 7;
            const __nv_bfloat16* src = (buf ? ql_g : qh_g) + gbase +
                                       (size_t)(q0 + row) * DM + cc * 8;
            CP_ASYNC16(sq + buf * QBUF_B + row * 144 + cc * 16, src);
        }
        CP_COMMIT();
        CP_WAIT(0);
        __syncthreads();
    }

    uint32_t qhf[4][4], qlf[4][4];
#pragma unroll
    for (int kc = 0; kc < 4; kc++) {
        uint32_t o = (aoff + (uint32_t)(wid * 16 * FLDS + kc * 16)) * 2;
        ldmx4(qhf[kc], sq + o);
        ldmx4(qlf[kc], sq + QBUF_B + o);
    }

    float acc[8][4];
#pragma unroll
    for (int f = 0; f < 8; f++)
#pragma unroll
        for (int r = 0; r < 4; r++) acc[f][r] = 0.0f;
    float m0 = -1e30f, m1 = -1e30f, l0 = 0.0f, l1 = 0.0f;

    const int T  = qb + 1;
    const int rr = lane >> 2, qx = lane & 3;
    const int rowg0 = q0 + wid * 16 + rr;

#pragma unroll 1
    for (int t = 0; t < T; t++) {
        if (t + 1 < T) {
            const uint32_t sb = skv + ((t + 1) & 1) * KVSTAGE_B;
            const int s1 = (t + 1) * 64;
#pragma unroll
            for (int kk = 0; kk < 16; kk++) {
                int id = tid + kk * 128;
                int buf = id >> 9, row = (id >> 3) & 63, cc = id & 7;
                CP_ASYNC16(sb + buf * KVBUF_B + row * 144 + cc * 16,
                           kvsrc[buf] + gbase + (size_t)(s1 + row) * DM + cc * 8);
            }
            CP_COMMIT();
            CP_WAIT(1);
        } else {
            CP_WAIT(0);
        }
        __syncthreads();

        const uint32_t st = skv + (t & 1) * KVSTAGE_B;

        float s[8][4];
#pragma unroll
        for (int f = 0; f < 8; f++)
#pragma unroll
            for (int r = 0; r < 4; r++) s[f][r] = 0.0f;

#pragma unroll
        for (int kc = 0; kc < 4; kc++) {
#pragma unroll
            for (int p = 0; p < 4; p++) {
                uint32_t o = (boff + (uint32_t)(p * 16 * FLDS + kc * 16)) * 2;
                uint32_t kbh[4], kbl[4];
                ldmx4(kbh, st + o);
                ldmx4(kbl, st + KVBUF_B + o);
                mma_bf16(s[2 * p],     qhf[kc], kbh[0], kbh[1]);
                mma_bf16(s[2 * p + 1], qhf[kc], kbh[2], kbh[3]);
                mma_bf16(s[2 * p],     qhf[kc], kbl[0], kbl[1]);
                mma_bf16(s[2 * p + 1], qhf[kc], kbl[2], kbl[3]);
                mma_bf16(s[2 * p],     qlf[kc], kbh[0], kbh[1]);
                mma_bf16(s[2 * p + 1], qlf[kc], kbh[2], kbh[3]);
            }
        }

        const int s0 = t * 64;
        if (s0 + 63 > q0) {
#pragma unroll
            for (int f = 0; f < 8; f++) {
                int c0 = s0 + f * 8 + 2 * qx;
                if (c0 > rowg0)         s[f][0] = -1e30f;
                if (c0 + 1 > rowg0)     s[f][1] = -1e30f;
                if (c0 > rowg0 + 8)     s[f][2] = -1e30f;
                if (c0 + 1 > rowg0 + 8) s[f][3] = -1e30f;
            }
        }

        {
            float mx = -1e30f;
#pragma unroll
            for (int f = 0; f < 8; f++) mx = fmaxf(mx, fmaxf(s[f][0], s[f][1]));
            mx = fmaxf(mx, __shfl_xor_sync(0xffffffffu, mx, 1));
            mx = fmaxf(mx, __shfl_xor_sync(0xffffffffu, mx, 2));
            float mn = fmaxf(m0, mx);
            float al = fexp2_raw(m0 - mn);
            m0 = mn;
            float sum = 0.0f;
#pragma unroll
            for (int f = 0; f < 8; f++) {
                s[f][0] = fexp2_raw(s[f][0] - mn);
                s[f][1] = fexp2_raw(s[f][1] - mn);
                sum += s[f][0] + s[f][1];
            }
            sum += __shfl_xor_sync(0xffffffffu, sum, 1);
            sum += __shfl_xor_sync(0xffffffffu, sum, 2);
            l0 = l0 * al + sum;
#pragma unroll
            for (int f = 0; f < 8; f++) { acc[f][0] *= al; acc[f][1] *= al; }
        }
        {
            float mx = -1e30f;
#pragma unroll
            for (int f = 0; f < 8; f++) mx = fmaxf(mx, fmaxf(s[f][2], s[f][3]));
            mx = fmaxf(mx, __shfl_xor_sync(0xffffffffu, mx, 1));
            mx = fmaxf(mx, __shfl_xor_sync(0xffffffffu, mx, 2));
            float mn = fmaxf(m1, mx);
            float al = fexp2_raw(m1 - mn);
            m1 = mn;
            float sum = 0.0f;
#pragma unroll
            for (int f = 0; f < 8; f++) {
                s[f][2] = fexp2_raw(s[f][2] - mn);
                s[f][3] = fexp2_raw(s[f][3] - mn);
                sum += s[f][2] + s[f][3];
            }
            sum += __shfl_xor_sync(0xffffffffu, sum, 1);
            sum += __shfl_xor_sync(0xffffffffu, sum, 2);
            l1 = l1 * al + sum;
#pragma unroll
            for (int f = 0; f < 8; f++) { acc[f][2] *= al; acc[f][3] *= al; }
        }

#pragma unroll
        for (int jc = 0; jc < 4; jc++) {
            const float* sA = s[2 * jc];
            const float* sB = s[2 * jc + 1];
            uint32_t pha[4], pla[4];
            pha[0] = pack_hi_trunc(sA[0], sA[1]);
            pha[1] = pack_hi_trunc(sA[2], sA[3]);
            pha[2] = pack_hi_trunc(sB[0], sB[1]);
            pha[3] = pack_hi_trunc(sB[2], sB[3]);
            pla[0] = packh(resid16(sA[0]), resid16(sA[1]));
            pla[1] = packh(resid16(sA[2]), resid16(sA[3]));
            pla[2] = packh(resid16(sB[0]), resid16(sB[1]));
            pla[3] = packh(resid16(sB[2]), resid16(sB[3]));
#pragma unroll
            for (int pe = 0; pe < 4; pe++) {
                uint32_t o = (aoff + (uint32_t)(jc * 16 * FLDS + pe * 16)) * 2;
                uint32_t vbh[4], vbl[4];
                ldmx4t(vbh, st + 2 * KVBUF_B + o);
                ldmx4t(vbl, st + 3 * KVBUF_B + o);
                mma_bf16(acc[2 * pe],     pha, vbh[0], vbh[1]);
                mma_bf16(acc[2 * pe + 1], pha, vbh[2], vbh[3]);
                mma_bf16(acc[2 * pe],     pha, vbl[0], vbl[1]);
                mma_bf16(acc[2 * pe + 1], pha, vbl[2], vbl[3]);
                mma_bf16(acc[2 * pe],     pla, vbh[0], vbh[1]);
                mma_bf16(acc[2 * pe + 1], pla, vbh[2], vbh[3]);
            }
        }
        __syncthreads();
    }

    const float inv0 = 1.0f / l0;
    const float inv1 = 1.0f / l1;
#pragma unroll
    for (int f = 0; f < 8; f++) {
        const int coloff = f * 8 + 2 * qx;
#pragma unroll
        for (int hrow = 0; hrow < 2; hrow++) {
            float inv = hrow ? inv1 : inv0;
            float v0 = acc[f][2 * hrow]     * inv;
            float v1 = acc[f][2 * hrow + 1] * inv;
            size_t off = gbase + (size_t)(rowg0 + 8 * hrow) * DM + coloff;
            *(uint32_t*)&ch_g[off] = pack_hi_trunc(v0, v1);
            *(uint32_t*)&cl_g[off] = packh(resid16(v0), resid16(v1));
        }
    }
}

// ---------------------------------------------------------------------------
extern "C" void kernel_launch(void* const* d_in, const int* in_sizes, int n_in,
                              void* d_out, int out_size)
{
    const float* x  = (const float*)d_in[0];
    const float* Wq = (const float*)d_in[1];
    const float* Wk = (const float*)d_in[2];
    const float* Wv = (const float*)d_in[3];
    const float* Wo = (const float*)d_in[4];
    float* out = (float*)d_out;

    __nv_bfloat16 *xh, *xl, *qh, *ql, *kh, *kl, *vh, *vl, *ch, *cl;
    __nv_bfloat16 *wqh, *wql, *wkh, *wkl, *wvh, *wvl, *woh, *wol;
    cudaGetSymbolAddress((void**)&xh, g_xh);
    cudaGetSymbolAddress((void**)&xl, g_xl);
    cudaGetSymbolAddress((void**)&qh, g_qh);
    cudaGetSymbolAddress((void**)&ql, g_ql);
    cudaGetSymbolAddress((void**)&kh, g_kh);
    cudaGetSymbolAddress((void**)&kl, g_kl);
    cudaGetSymbolAddress((void**)&vh, g_vh);
    cudaGetSymbolAddress((void**)&vl, g_vl);
    cudaGetSymbolAddress((void**)&ch, g_ch);
    cudaGetSymbolAddress((void**)&cl, g_cl);
    cudaGetSymbolAddress((void**)&wqh, g_wqh);
    cudaGetSymbolAddress((void**)&wql, g_wql);
    cudaGetSymbolAddress((void**)&wkh, g_wkh);
    cudaGetSymbolAddress((void**)&wkl, g_wkl);
    cudaGetSymbolAddress((void**)&wvh, g_wvh);
    cudaGetSymbolAddress((void**)&wvl, g_wvl);
    cudaGetSymbolAddress((void**)&woh, g_woh);
    cudaGetSymbolAddress((void**)&wol, g_wol);

    cudaFuncSetAttribute(gemm_qkv,
                         cudaFuncAttributeMaxDynamicSharedMemorySize, GEMM_SMEM);
    cudaFuncSetAttribute(gemm_out,
                         cudaFuncAttributeMaxDynamicSharedMemorySize, GEMM_SMEM);
    cudaFuncSetAttribute(flash_mma,
                         cudaFuncAttributeMaxDynamicSharedMemorySize, FLASH_SMEM);

    const int M  = BATCH * SEQ;           // 8192
    const int n4x = M * DM / 4;
    const int n4w = DM * DM / 4;

    // fp32 -> bf16 hi/lo splits
    split_f32<<<n4x / 256, 256>>>(x, xh, xl, n4x);
    split_w4<<<dim3(n4w / 256, 4), 256>>>(Wq, Wk, Wv, Wo,
                                          wqh, wql, wkh, wkl,
                                          wvh, wvl, woh, wol, n4w);

    // Fused QKV projections: 64x128-tile small CTAs, 3/SM co-resident
    dim3 gqkv(DM / 128, M / 64, 3);       // (8, 128, 3) = 3072 CTAs
    gemm_qkv<<<gqkv, 128, GEMM_SMEM>>>(xh, xl,
                                       wqh, wql, wkh, wkl, wvh, wvl,
                                       qh, ql, kh, kl, vh, vl);

    // causal attention: 128-thread CTAs, 2/SM co-resident
    flash_mma<<<dim3(SEQ / 64, BATCH * NH), 128, FLASH_SMEM>>>(
        qh, ql, kh, kl, vh, vl, ch, cl);

    // output projection (fp32 out)
    gemm_out<<<dim3(DM / 128, M / 64), 128, GEMM_SMEM>>>(ch, cl, woh, wol, out);
}